// round 9
// baseline (speedup 1.0000x reference)
#include <cuda_runtime.h>
#include <math.h>

typedef unsigned long long ull;

#define NBATCH 2048
#define NPAIR 1024

// ---------------- device scratch ----------------
__device__ __align__(16) ull g_wA[2700];                             // composed 5x5 weights (w,w) pairs
__device__ float g_b2[18];                                           // composed bias
__device__ __align__(16) ull g_pool1p[(size_t)NPAIR * 18 * 30 * 30]; // pool1, sample-pair interleaved
__device__ __align__(16) ull g_zp[(size_t)NPAIR * 18 * 28 * 28];     // conv3 out, interleaved
__device__ __align__(16) float g_feat[(size_t)NBATCH * 3042];        // flattened features

// ---------------- packed f32x2 helpers ----------------
__device__ __forceinline__ void ffma2(ull& d, ull a, ull b) {
    asm("fma.rn.f32x2 %0, %1, %2, %0;" : "+l"(d) : "l"(a), "l"(b));
}
__device__ __forceinline__ ull pk2(float lo, float hi) {
    ull r;
    asm("mov.b64 %0, {%1, %2};" : "=l"(r) : "f"(lo), "f"(hi));
    return r;
}
__device__ __forceinline__ float2 upk2(ull v) {
    float2 r;
    asm("mov.b64 {%0, %1}, %2;" : "=f"(r.x), "=f"(r.y) : "l"(v));
    return r;
}

// ---------------- compose conv1*conv2 -> one 5x5 conv ----------------
__global__ void k_compose(const float* __restrict__ c1w, const float* __restrict__ c1b,
                          const float* __restrict__ c2w, const float* __restrict__ c2b) {
    int idx = blockIdx.x * blockDim.x + threadIdx.x;
    if (idx < 2700) {
        int o = idx / 150;
        int ci = (idx / 25) % 6;
        int y = (idx % 25) / 5;
        int x = idx % 5;
        int ky_lo = y > 2 ? y - 2 : 0, ky_hi = y < 2 ? y : 2;
        int kx_lo = x > 2 ? x - 2 : 0, kx_hi = x < 2 ? x : 2;
        float s = 0.f;
        for (int m = 0; m < 18; m++)
            for (int ky = ky_lo; ky <= ky_hi; ky++)
                for (int kx = kx_lo; kx <= kx_hi; kx++)
                    s += c1w[((m * 6 + ci) * 3 + ky) * 3 + kx] *
                         c2w[((o * 18 + m) * 3 + (y - ky)) * 3 + (x - kx)];
        g_wA[idx] = pk2(s, s);
    } else if (idx < 2718) {
        int o = idx - 2700;
        float s = c2b[o];
        for (int m = 0; m < 18; m++) {
            float t = 0.f;
            for (int q = 0; q < 9; q++) t += c2w[(o * 18 + m) * 9 + q];
            s += c1b[m] * t;
        }
        g_b2[o] = s;
    }
}

// ---------------- convA v2: composed 5x5 (6->18) + maxpool2, 2 oc/thread ----------------
// grid (10 bands of 3 pooled rows, 1024 pairs), 288 thr, 2 CTAs/SM
// smem: W2ps 21600 | b2s 96 | inP 6*10*66 ull = 31680  => 53376
#define SMEM_A 53376

__global__ __launch_bounds__(288, 2) void k_convA(const float* __restrict__ states) {
    extern __shared__ char smA[];
    ull* W2ps = (ull*)smA;
    float* b2s = (float*)(smA + 21600);
    ull* inP = (ull*)(smA + 21696);
    const int tid = threadIdx.x;
    const int band = blockIdx.x;       // pooled rows 3b..3b+2, input rows 6b..6b+9
    const int pair = blockIdx.y;
    const int ir0 = 6 * band;

    for (int i = tid; i < 2700; i += 288) W2ps[i] = g_wA[i];
    if (tid < 18) b2s[tid] = g_b2[tid];
    {
        const float4* s0 = (const float4*)(states) + (size_t)pair * 12288;
        // 6 ci x 10 rows x 16 float4-groups
        for (int j = tid; j < 960; j += 288) {
            int c4 = j & 15, row = (j >> 4) % 10, ci = j / 160;
            int goff = (ci * 64 + ir0 + row) * 16 + c4;
            float4 a = s0[goff], b = s0[goff + 6144];
            ull* d = inP + ci * 660 + row * 66 + c4 * 4;
            d[0] = pk2(a.x, b.x); d[1] = pk2(a.y, b.y);
            d[2] = pk2(a.z, b.z); d[3] = pk2(a.w, b.w);
        }
    }
    __syncthreads();

    // strips: ocp(9) x blk(10) x pl(3) = 270; ocp slowest => weights warp-broadcast
    if (tid < 270) {
        const int ocp = tid / 30;
        const int rem = tid - ocp * 30;
        const int blk = rem / 3;
        const int pl = rem - blk * 3;
        const int c0 = blk * 6;

        ull acc[2][2][6];
#pragma unroll
        for (int o = 0; o < 2; o++)
#pragma unroll
            for (int rr = 0; rr < 2; rr++)
#pragma unroll
                for (int j = 0; j < 6; j++) acc[o][rr][j] = 0ull;

#pragma unroll 1
        for (int ci = 0; ci < 6; ci++) {
            const ull* rb = inP + ci * 660 + pl * 132 + c0;  // 2*pl rows * 66
            const ull* wc0 = W2ps + (2 * ocp) * 150 + ci * 25;
            const ull* wc1 = wc0 + 150;
#pragma unroll
            for (int iy = 0; iy < 6; iy++) {
                ull v[10];
                {
                    const ull* vp = rb + iy * 66;
#pragma unroll
                    for (int j = 0; j < 10; j++) v[j] = vp[j];
                }
                if (iy < 5) {
#pragma unroll
                    for (int kx = 0; kx < 5; kx++) {
                        ull w0 = wc0[iy * 5 + kx], w1 = wc1[iy * 5 + kx];
#pragma unroll
                        for (int j = 0; j < 6; j++) {
                            ffma2(acc[0][0][j], w0, v[j + kx]);
                            ffma2(acc[1][0][j], w1, v[j + kx]);
                        }
                    }
                }
                if (iy >= 1) {
#pragma unroll
                    for (int kx = 0; kx < 5; kx++) {
                        ull w0 = wc0[(iy - 1) * 5 + kx], w1 = wc1[(iy - 1) * 5 + kx];
#pragma unroll
                        for (int j = 0; j < 6; j++) {
                            ffma2(acc[0][1][j], w0, v[j + kx]);
                            ffma2(acc[1][1][j], w1, v[j + kx]);
                        }
                    }
                }
            }
        }
        const int prow = band * 3 + pl;
#pragma unroll
        for (int o = 0; o < 2; o++) {
            int oc = 2 * ocp + o;
            float bias = b2s[oc];
            ull* op = g_pool1p + (((size_t)pair * 18 + oc) * 30 + prow) * 30 + blk * 3;
#pragma unroll
            for (int p = 0; p < 3; p++) {
                float2 a0 = upk2(acc[o][0][2 * p]), a1 = upk2(acc[o][0][2 * p + 1]);
                float2 b0 = upk2(acc[o][1][2 * p]), b1 = upk2(acc[o][1][2 * p + 1]);
                float2 m;
                m.x = fmaxf(fmaxf(a0.x, a1.x), fmaxf(b0.x, b1.x)) + bias;
                m.y = fmaxf(fmaxf(a0.y, a1.y), fmaxf(b0.y, b1.y)) + bias;
                ((float2*)op)[p] = m;
            }
        }
    }
}

// ---------------- conv3 v2: 18->18, 30x30 -> 28x28, 2 oc/thread ----------------
// grid (2 rowhalves, 1024 pairs), 256 thr, 2 CTAs/SM
// smem: w3p 23328 | b3 96 | pS 18*16*33 ull = 76032  => 99456
#define SMEM_C3 99456

__global__ __launch_bounds__(256, 2) void k_conv3(const float* __restrict__ c3w, const float* __restrict__ c3b) {
    extern __shared__ char smC[];
    ull* w3p = (ull*)smC;
    float* b3s = (float*)(smC + 23328);
    ull* pS = (ull*)(smC + 23424);
    const int tid = threadIdx.x;
    const int hf = blockIdx.x;         // 0: out rows 0..13, 1: out rows 14..27
    const int pair = blockIdx.y;
    const int ir0 = 14 * hf;

    for (int i = tid; i < 2916; i += 256) { float w = c3w[i]; w3p[i] = pk2(w, w); }
    if (tid < 18) b3s[tid] = c3b[tid];
    {
        const ull* src = g_pool1p + (size_t)pair * 16200;
        for (int e = tid; e < 8640; e += 256) {
            int c = e % 30;
            int r = (e / 30) & 15;
            int ci = e / 480;
            pS[ci * 528 + r * 33 + c] = src[(ci * 30 + ir0 + r) * 30 + c];
        }
    }
    __syncthreads();

    // strips: ocp(9) x rl(7) x cq(4) = 252; ocp slowest
    if (tid < 252) {
        const int ocp = tid / 28;
        const int rem = tid - ocp * 28;
        const int rl = rem / 4;
        const int cq = rem - rl * 4;
        const int c0 = cq * 7;

        ull acc[2][2][7];
#pragma unroll
        for (int o = 0; o < 2; o++)
#pragma unroll
            for (int rr = 0; rr < 2; rr++)
#pragma unroll
                for (int j = 0; j < 7; j++) acc[o][rr][j] = 0ull;

#pragma unroll 1
        for (int ci = 0; ci < 18; ci++) {
            const ull* rb = pS + ci * 528 + rl * 66 + c0;   // 2*rl rows * 33
            const ull* wc0 = w3p + (2 * ocp) * 162 + ci * 9;
            const ull* wc1 = wc0 + 162;
#pragma unroll
            for (int iy = 0; iy < 4; iy++) {
                ull v[9];
                {
                    const ull* vp = rb + iy * 33;
#pragma unroll
                    for (int j = 0; j < 9; j++) v[j] = vp[j];
                }
                if (iy < 3) {
#pragma unroll
                    for (int kx = 0; kx < 3; kx++) {
                        ull w0 = wc0[iy * 3 + kx], w1 = wc1[iy * 3 + kx];
#pragma unroll
                        for (int j = 0; j < 7; j++) {
                            ffma2(acc[0][0][j], w0, v[j + kx]);
                            ffma2(acc[1][0][j], w1, v[j + kx]);
                        }
                    }
                }
                if (iy >= 1) {
#pragma unroll
                    for (int kx = 0; kx < 3; kx++) {
                        ull w0 = wc0[(iy - 1) * 3 + kx], w1 = wc1[(iy - 1) * 3 + kx];
#pragma unroll
                        for (int j = 0; j < 7; j++) {
                            ffma2(acc[0][1][j], w0, v[j + kx]);
                            ffma2(acc[1][1][j], w1, v[j + kx]);
                        }
                    }
                }
            }
        }
        const int orow0 = 2 * (7 * hf + rl);
#pragma unroll
        for (int o = 0; o < 2; o++) {
            int oc = 2 * ocp + o;
            float b = b3s[oc];
            ull* zb = g_zp + (((size_t)pair * 18 + oc) * 28 + orow0) * 28 + c0;
#pragma unroll
            for (int rr = 0; rr < 2; rr++)
#pragma unroll
                for (int j = 0; j < 7; j++) {
                    float2 vv = upk2(acc[o][rr][j]);
                    ((float2*)zb)[rr * 28 + j] = make_float2(vv.x + b, vv.y + b);
                }
        }
    }
}

// ---------------- 3x3 pair-conv strip (rolling weight rows) — R4 conv4 helper ----------------
template <int COLS, bool ALIGNED>
__device__ __forceinline__ void conv3x3_pair(const ull* rb, int rstride, const ull* wc,
                                             ull (&acc)[2][COLS]) {
    ull wn0 = 0, wn1 = 0, wn2 = 0, wp0 = 0, wp1 = 0, wp2 = 0;
#pragma unroll
    for (int iy = 0; iy < 4; iy++) {
        ull v[COLS + 2];
        if (ALIGNED) {
            const ulonglong2* vp = (const ulonglong2*)(rb + iy * rstride);
#pragma unroll
            for (int j = 0; j < (COLS + 2) / 2; j++) { ulonglong2 q = vp[j]; v[2 * j] = q.x; v[2 * j + 1] = q.y; }
        } else {
#pragma unroll
            for (int j = 0; j < COLS + 2; j++) v[j] = rb[iy * rstride + j];
        }
        if (iy < 3) {
            wn0 = wc[iy * 3]; wn1 = wc[iy * 3 + 1]; wn2 = wc[iy * 3 + 2];
#pragma unroll
            for (int j = 0; j < COLS; j++) {
                ffma2(acc[0][j], wn0, v[j]);
                ffma2(acc[0][j], wn1, v[j + 1]);
                ffma2(acc[0][j], wn2, v[j + 2]);
            }
        }
        if (iy >= 1) {
#pragma unroll
            for (int j = 0; j < COLS; j++) {
                ffma2(acc[1][j], wp0, v[j]);
                ffma2(acc[1][j], wp1, v[j + 1]);
                ffma2(acc[1][j], wp2, v[j + 2]);
            }
        }
        wp0 = wn0; wp1 = wn1; wp2 = wn2;
    }
}

// ---------------- conv4 (R4 version, verbatim): 18->18, 28x28 -> 26x26 + avgpool -> 13x13 ----------------
// grid (2 rowhalves, 1024 pairs), 512 thr, 2 CTAs/SM
// smem: w4p 23328 | b4 96 | zS 18*16*28 ull = 64512  => 87936
#define SMEM_C4 87936

__global__ __launch_bounds__(512, 2) void k_conv4(const float* __restrict__ c4w, const float* __restrict__ c4b) {
    extern __shared__ char smD[];
    ull* w4p = (ull*)smD;
    float* b4s = (float*)(smD + 23328);
    ull* zS = (ull*)(smD + 23424);
    const int tid = threadIdx.x;
    const int hf = blockIdx.x;         // 0: prow 0..6, 1: prow 7..12
    const int pair = blockIdx.y;
    const int ir0 = 14 * hf;
    const int nr = 16 - 2 * hf;        // rows loaded: 16 / 14

    for (int i = tid; i < 2916; i += 512) { float w = c4w[i]; w4p[i] = pk2(w, w); }
    if (tid < 18) b4s[tid] = c4b[tid];
    {
        int per_ci = nr * 14;  // ulonglong2 units per ci
        int total = 18 * per_ci;
        for (int i = tid; i < total; i += 512) {
            int ci = i / per_ci, rem = i - ci * per_ci;
            const ulonglong2* src = (const ulonglong2*)(g_zp + (size_t)pair * 14112 + ci * 784 + ir0 * 28);
            ((ulonglong2*)(zS + ci * 448))[rem] = src[rem];
        }
    }
    __syncthreads();

    // strips: rl(7 or 6) x cq(4) x oc(18); COLS=8 overlapping quarters (c0 = 6*cq)
    int nstrip = (hf ? 6 : 7) * 4 * 18;
    if (tid < nstrip) {
        int oc = tid % 18;
        int r2 = tid / 18;
        int cq = r2 % 4;
        int rl = r2 / 4;
        int c0 = cq * 6;

        ull acc[2][8];
#pragma unroll
        for (int r = 0; r < 2; r++)
#pragma unroll
            for (int j = 0; j < 8; j++) acc[r][j] = 0ull;

#pragma unroll 1
        for (int ci = 0; ci < 18; ci++)
            conv3x3_pair<8, true>(zS + ci * 448 + rl * 56 + c0, 28, w4p + (oc * 18 + ci) * 9, acc);

        float b = b4s[oc];
        int prow = 7 * hf + rl;
        float* f0 = g_feat + (size_t)(2 * pair) * 3042 + (oc * 13 + prow) * 13;
        float* f1 = f0 + 3042;
        int plo = cq ? 1 : 0;
#pragma unroll
        for (int pp = 0; pp < 4; pp++) {
            if (pp >= plo) {
                float2 a0 = upk2(acc[0][2 * pp]), a1 = upk2(acc[0][2 * pp + 1]);
                float2 b0 = upk2(acc[1][2 * pp]), b1 = upk2(acc[1][2 * pp + 1]);
                f0[3 * cq + pp] = 0.25f * (a0.x + a1.x + b0.x + b1.x) + b;
                f1[3 * cq + pp] = 0.25f * (a0.y + a1.y + b0.y + b1.y) + b;
            }
        }
    }
}

// ---------------- MLP + expert routing + softmax, 8 samples/CTA (R4 verbatim) ----------------
#define SMEM_M ((8 * 3076 + 64 * 132 + 8 * 66 + 512 + 64) * 4)

__global__ __launch_bounds__(512, 1) void k_mlp(const float* __restrict__ scores, const float* __restrict__ times,
                                                const int* __restrict__ agents,
                                                const float* __restrict__ l1w, const float* __restrict__ l1b,
                                                const float* __restrict__ l2w, const float* __restrict__ l2b,
                                                const float* __restrict__ agw, const float* __restrict__ agb,
                                                float* __restrict__ out) {
    extern __shared__ float smM[];
    float* featS = smM;                       // stride 3076 per sample
    float* wT = featS + 8 * 3076;             // 64 x 132
    float* h1S = wT + 64 * 132;               // stride 66
    float* h2S = h1S + 8 * 66;                // stride 64
    float* logS = h2S + 512;
    const int tid = threadIdx.x;
    const int sb = blockIdx.x * 8;

    for (int i = tid; i < 8 * 1521; i += 512) {
        int s = i / 1521;
        int r = i - s * 1521;
        ((float2*)(featS + s * 3076))[r] = ((const float2*)(g_feat + (size_t)(sb + s) * 3042))[r];
    }
    if (tid < 8) {
        featS[tid * 3076 + 3042] = scores[sb + tid];
        featS[tid * 3076 + 3043] = times[sb + tid];
    }
    if (tid >= 32 && tid < 288) {
        int j = tid - 32;                     // zero-pad k = 3044..3075
        featS[(j >> 5) * 3076 + 3044 + (j & 31)] = 0.f;
    }
    __syncthreads();

    const int s = tid & 7, o = tid >> 3;      // o 0..63; 8 lanes per o broadcast
    ull f0a = 0, f1a = 0, f2a = 0, f3a = 0;
#pragma unroll 1
    for (int kt = 0; kt < 24; kt++) {
        int k0 = kt << 7;
        for (int i = tid; i < 8192; i += 512) {
            int oo = i >> 7, kk = i & 127;
            int k = k0 + kk;
            wT[oo * 132 + kk] = (k < 3044) ? l1w[oo * 3044 + k] : 0.f;
        }
        __syncthreads();
        const ull* fr = (const ull*)(featS + s * 3076 + k0);
        const ull* wr = (const ull*)(wT + o * 132);
#pragma unroll
        for (int kk = 0; kk < 64; kk += 4) {
            ffma2(f0a, fr[kk], wr[kk]);
            ffma2(f1a, fr[kk + 1], wr[kk + 1]);
            ffma2(f2a, fr[kk + 2], wr[kk + 2]);
            ffma2(f3a, fr[kk + 3], wr[kk + 3]);
        }
        __syncthreads();
    }
    {
        float2 a = upk2(f0a), b = upk2(f1a), c = upk2(f2a), d = upk2(f3a);
        float acc = (a.x + a.y) + (b.x + b.y) + (c.x + c.y) + (d.x + d.y);
        h1S[s * 66 + o] = tanhf(acc + l1b[o]);
    }
    __syncthreads();
    {
        const ull* hr = (const ull*)(h1S + s * 66);
        const ull* w2 = (const ull*)(l2w + o * 64);
        ull a0 = 0, a1 = 0;
#pragma unroll
        for (int kk = 0; kk < 32; kk += 2) {
            ffma2(a0, hr[kk], w2[kk]);
            ffma2(a1, hr[kk + 1], w2[kk + 1]);
        }
        float2 a = upk2(a0), b = upk2(a1);
        h2S[s * 64 + o] = tanhf(a.x + a.y + b.x + b.y + l2b[o]);
    }
    __syncthreads();
    if (tid < 40) {
        int ss = tid / 5, oo = tid - ss * 5;
        int ag = agents[sb + ss];
        const float* W = agw + (ag * 5 + oo) * 64;
        const float* h = h2S + ss * 64;
        float a = agb[ag * 5 + oo];
#pragma unroll
        for (int k = 0; k < 64; k++) a += W[k] * h[k];
        logS[ss * 8 + oo] = a;
    }
    __syncthreads();
    if (tid < 8) {
        float m = -1e30f;
        for (int i = 0; i < 5; i++) m = fmaxf(m, logS[tid * 8 + i]);
        float e[5], sum = 0.f;
        for (int i = 0; i < 5; i++) { e[i] = expf(logS[tid * 8 + i] - m); sum += e[i]; }
        float inv = 1.f / sum;
        for (int i = 0; i < 5; i++) out[(sb + tid) * 5 + i] = e[i] * inv;
    }
}

// ---------------- launch ----------------
extern "C" void kernel_launch(void* const* d_in, const int* in_sizes, int n_in,
                              void* d_out, int out_size) {
    const float* states = (const float*)d_in[0];
    const float* scores = (const float*)d_in[1];
    const float* times  = (const float*)d_in[2];
    const int*   agents = (const int*)d_in[3];
    const float* c1w = (const float*)d_in[4];
    const float* c1b = (const float*)d_in[5];
    const float* c2w = (const float*)d_in[6];
    const float* c2b = (const float*)d_in[7];
    const float* c3w = (const float*)d_in[8];
    const float* c3b = (const float*)d_in[9];
    const float* c4w = (const float*)d_in[10];
    const float* c4b = (const float*)d_in[11];
    const float* l1w = (const float*)d_in[12];
    const float* l1b = (const float*)d_in[13];
    const float* l2w = (const float*)d_in[14];
    const float* l2b = (const float*)d_in[15];
    const float* agw = (const float*)d_in[16];
    const float* agb = (const float*)d_in[17];
    float* out = (float*)d_out;

    cudaFuncSetAttribute(k_convA, cudaFuncAttributeMaxDynamicSharedMemorySize, SMEM_A);
    cudaFuncSetAttribute(k_conv3, cudaFuncAttributeMaxDynamicSharedMemorySize, SMEM_C3);
    cudaFuncSetAttribute(k_conv4, cudaFuncAttributeMaxDynamicSharedMemorySize, SMEM_C4);
    cudaFuncSetAttribute(k_mlp, cudaFuncAttributeMaxDynamicSharedMemorySize, SMEM_M);

    k_compose<<<3, 1024>>>(c1w, c1b, c2w, c2b);
    k_convA<<<dim3(10, 1024), 288, SMEM_A>>>(states);
    k_conv3<<<dim3(2, 1024), 256, SMEM_C3>>>(c3w, c3b);
    k_conv4<<<dim3(2, 1024), 512, SMEM_C4>>>(c4w, c4b);
    k_mlp<<<256, 512, SMEM_M>>>(scores, times, agents, l1w, l1b, l2w, l2b, agw, agb, out);
}

// round 10
// speedup vs baseline: 1.1494x; 1.1494x over previous
#include <cuda_runtime.h>
#include <math.h>

typedef unsigned long long ull;

#define NBATCH 2048
#define NPAIR 1024

// ---------------- device scratch ----------------
__device__ __align__(16) ull g_wA[2700];                             // composed 5x5 weights (w,w) pairs
__device__ float g_b2[18];                                           // composed bias
__device__ __align__(16) ull g_pool1p[(size_t)NPAIR * 18 * 30 * 30]; // pool1, sample-pair interleaved
__device__ __align__(16) ull g_zp[(size_t)NPAIR * 18 * 28 * 28];     // conv3 out, interleaved
__device__ __align__(16) float g_feat[(size_t)NBATCH * 3042];        // flattened features

// ---------------- packed f32x2 helpers ----------------
__device__ __forceinline__ void ffma2(ull& d, ull a, ull b) {
    asm("fma.rn.f32x2 %0, %1, %2, %0;" : "+l"(d) : "l"(a), "l"(b));
}
__device__ __forceinline__ ull pk2(float lo, float hi) {
    ull r;
    asm("mov.b64 %0, {%1, %2};" : "=l"(r) : "f"(lo), "f"(hi));
    return r;
}
__device__ __forceinline__ float2 upk2(ull v) {
    float2 r;
    asm("mov.b64 {%0, %1}, %2;" : "=f"(r.x), "=f"(r.y) : "l"(v));
    return r;
}

// ---------------- compose conv1*conv2 -> one 5x5 conv ----------------
__global__ void k_compose(const float* __restrict__ c1w, const float* __restrict__ c1b,
                          const float* __restrict__ c2w, const float* __restrict__ c2b) {
    int idx = blockIdx.x * blockDim.x + threadIdx.x;
    if (idx < 2700) {
        int o = idx / 150;
        int ci = (idx / 25) % 6;
        int y = (idx % 25) / 5;
        int x = idx % 5;
        int ky_lo = y > 2 ? y - 2 : 0, ky_hi = y < 2 ? y : 2;
        int kx_lo = x > 2 ? x - 2 : 0, kx_hi = x < 2 ? x : 2;
        float s = 0.f;
        for (int m = 0; m < 18; m++)
            for (int ky = ky_lo; ky <= ky_hi; ky++)
                for (int kx = kx_lo; kx <= kx_hi; kx++)
                    s += c1w[((m * 6 + ci) * 3 + ky) * 3 + kx] *
                         c2w[((o * 18 + m) * 3 + (y - ky)) * 3 + (x - kx)];
        g_wA[idx] = pk2(s, s);
    } else if (idx < 2718) {
        int o = idx - 2700;
        float s = c2b[o];
        for (int m = 0; m < 18; m++) {
            float t = 0.f;
            for (int q = 0; q < 9; q++) t += c2w[(o * 18 + m) * 9 + q];
            s += c1b[m] * t;
        }
        g_b2[o] = s;
    }
}

// ---------------- convA: composed 5x5 (6->18) + maxpool2 — balanced strips ----------------
// grid (6 bands of 5 pooled rows, 1024 pairs), 480 thr, 2 CTAs/SM
// strips = 5*10*18 = 900 over 480 threads -> max 2 passes (93.75% balance)
// smem: W2ps 21600 | b2s 96 | inP 6*14*64 ull = 43008  => 64704
#define SMEM_A 64704

__global__ __launch_bounds__(480, 2) void k_convA(const float* __restrict__ states) {
    extern __shared__ char smA[];
    ull* W2ps = (ull*)smA;
    float* b2s = (float*)(smA + 21600);
    ull* inP = (ull*)(smA + 21696);
    const int tid = threadIdx.x;
    const int band = blockIdx.x;       // pooled rows 5b..5b+4, input rows 10b..10b+13
    const int pair = blockIdx.y;
    const int ir0 = 10 * band;

    for (int i = tid; i < 2700; i += 480) W2ps[i] = g_wA[i];
    if (tid < 18) b2s[tid] = g_b2[tid];
    {
        const float4* s0 = (const float4*)(states) + (size_t)pair * 12288;
        // 6 ci x 14 rows x 16 float4-groups = 1344 iterations
        for (int i = tid; i < 1344; i += 480) {
            int c4 = i & 15, r = (i >> 4) % 14, ci = i / 224;
            int goff = (ci * 64 + ir0 + r) * 16 + c4;
            float4 a = s0[goff], b = s0[goff + 6144];
            ull* d = inP + ci * 896 + r * 64 + c4 * 4;
            d[0] = pk2(a.x, b.x); d[1] = pk2(a.y, b.y);
            d[2] = pk2(a.z, b.z); d[3] = pk2(a.w, b.w);
        }
    }
    __syncthreads();

    // strips: pl(5) x blk(10) x oc(18) = 900; oc fastest (warp-broadcast data LDS)
    for (int t = tid; t < 900; t += 480) {
        int oc = t % 18;
        int r2 = t / 18;
        int blk = r2 % 10;
        int pl = r2 / 10;          // local pooled row 0..4
        int c0 = blk * 6;

        ull acc[2][6];
#pragma unroll
        for (int r = 0; r < 2; r++)
#pragma unroll
            for (int j = 0; j < 6; j++) acc[r][j] = 0ull;

#pragma unroll 1
        for (int ci = 0; ci < 6; ci++) {
            const ull* rb = inP + ci * 896 + pl * 128 + c0;   // 2*pl rows * 64
            const ull* wc = W2ps + oc * 150 + ci * 25;
#pragma unroll
            for (int iy = 0; iy < 6; iy++) {
                ull v[10];
                {
                    const ull* vp = rb + (iy << 6);
#pragma unroll
                    for (int j = 0; j < 10; j++) v[j] = vp[j];
                }
                if (iy < 5) {
#pragma unroll
                    for (int kx = 0; kx < 5; kx++) {
                        ull w = wc[iy * 5 + kx];
#pragma unroll
                        for (int j = 0; j < 6; j++) ffma2(acc[0][j], w, v[j + kx]);
                    }
                }
                if (iy >= 1) {
#pragma unroll
                    for (int kx = 0; kx < 5; kx++) {
                        ull w = wc[(iy - 1) * 5 + kx];
#pragma unroll
                        for (int j = 0; j < 6; j++) ffma2(acc[1][j], w, v[j + kx]);
                    }
                }
            }
        }
        float bias = b2s[oc];
        int prow = band * 5 + pl;
        ull* op = g_pool1p + (((size_t)pair * 18 + oc) * 30 + prow) * 30 + blk * 3;
#pragma unroll
        for (int p = 0; p < 3; p++) {
            float2 a0 = upk2(acc[0][2 * p]), a1 = upk2(acc[0][2 * p + 1]);
            float2 b0 = upk2(acc[1][2 * p]), b1 = upk2(acc[1][2 * p + 1]);
            float2 m;
            m.x = fmaxf(fmaxf(a0.x, a1.x), fmaxf(b0.x, b1.x)) + bias;
            m.y = fmaxf(fmaxf(a0.y, a1.y), fmaxf(b0.y, b1.y)) + bias;
            ((float2*)op)[p] = m;
        }
    }
}

// ---------------- 3x3 pair-conv strip (rolling weight rows) ----------------
template <int COLS, bool ALIGNED>
__device__ __forceinline__ void conv3x3_pair(const ull* rb, int rstride, const ull* wc,
                                             ull (&acc)[2][COLS]) {
    ull wn0 = 0, wn1 = 0, wn2 = 0, wp0 = 0, wp1 = 0, wp2 = 0;
#pragma unroll
    for (int iy = 0; iy < 4; iy++) {
        ull v[COLS + 2];
        if (ALIGNED) {
            const ulonglong2* vp = (const ulonglong2*)(rb + iy * rstride);
#pragma unroll
            for (int j = 0; j < (COLS + 2) / 2; j++) { ulonglong2 q = vp[j]; v[2 * j] = q.x; v[2 * j + 1] = q.y; }
        } else {
#pragma unroll
            for (int j = 0; j < COLS + 2; j++) v[j] = rb[iy * rstride + j];
        }
        if (iy < 3) {
            wn0 = wc[iy * 3]; wn1 = wc[iy * 3 + 1]; wn2 = wc[iy * 3 + 2];
#pragma unroll
            for (int j = 0; j < COLS; j++) {
                ffma2(acc[0][j], wn0, v[j]);
                ffma2(acc[0][j], wn1, v[j + 1]);
                ffma2(acc[0][j], wn2, v[j + 2]);
            }
        }
        if (iy >= 1) {
#pragma unroll
            for (int j = 0; j < COLS; j++) {
                ffma2(acc[1][j], wp0, v[j]);
                ffma2(acc[1][j], wp1, v[j + 1]);
                ffma2(acc[1][j], wp2, v[j + 2]);
            }
        }
        wp0 = wn0; wp1 = wn1; wp2 = wn2;
    }
}

// ---------------- conv3 (R4 verbatim): 18->18, 30x30 -> 28x28 ----------------
// grid (2 rowhalves, 1024 pairs), 512 thr, 2 CTAs/SM
// smem: w3p 23328 | b3 96 | pS 18*16*32 ull = 73728  => 97152
#define SMEM_C3 97152

__global__ __launch_bounds__(512, 2) void k_conv3(const float* __restrict__ c3w, const float* __restrict__ c3b) {
    extern __shared__ char smC[];
    ull* w3p = (ull*)smC;
    float* b3s = (float*)(smC + 23328);
    ull* pS = (ull*)(smC + 23424);
    const int tid = threadIdx.x;
    const int hf = blockIdx.x;         // 0: rowp 0..6, 1: rowp 7..13
    const int pair = blockIdx.y;
    const int ir0 = 14 * hf;

    for (int i = tid; i < 2916; i += 512) { float w = c3w[i]; w3p[i] = pk2(w, w); }
    if (tid < 18) b3s[tid] = c3b[tid];
    {
        const ull* src = g_pool1p + (size_t)pair * 16200;
        for (int e = tid; e < 8640; e += 512) {
            int c = e % 30;
            int r = (e / 30) & 15;
            int ci = e / 480;
            pS[ci * 512 + r * 32 + c] = src[(ci * 30 + ir0 + r) * 30 + c];
        }
    }
    __syncthreads();

    // strips: rl(7) x cq(4) x oc(18) = 504
    if (tid < 504) {
        int oc = tid % 18;
        int r2 = tid / 18;
        int cq = r2 % 4;
        int rl = r2 / 4;
        int c0 = cq * 7;

        ull acc[2][7];
#pragma unroll
        for (int r = 0; r < 2; r++)
#pragma unroll
            for (int j = 0; j < 7; j++) acc[r][j] = 0ull;

#pragma unroll 1
        for (int ci = 0; ci < 18; ci++)
            conv3x3_pair<7, false>(pS + ci * 512 + rl * 64 + c0, 32, w3p + (oc * 18 + ci) * 9, acc);

        float b = b3s[oc];
        int orow = 2 * (7 * hf + rl);
        ull* zb = g_zp + (((size_t)pair * 18 + oc) * 28 + orow) * 28 + c0;
#pragma unroll
        for (int r = 0; r < 2; r++)
#pragma unroll
            for (int j = 0; j < 7; j++) {
                float2 vv = upk2(acc[r][j]);
                ((float2*)zb)[r * 28 + j] = make_float2(vv.x + b, vv.y + b);
            }
    }
}

// ---------------- conv4 (R4 verbatim): 18->18, 28x28 -> 26x26 + avgpool -> 13x13 ----------------
// grid (2 rowhalves, 1024 pairs), 512 thr, 2 CTAs/SM
// smem: w4p 23328 | b4 96 | zS 18*16*28 ull = 64512  => 87936
#define SMEM_C4 87936

__global__ __launch_bounds__(512, 2) void k_conv4(const float* __restrict__ c4w, const float* __restrict__ c4b) {
    extern __shared__ char smD[];
    ull* w4p = (ull*)smD;
    float* b4s = (float*)(smD + 23328);
    ull* zS = (ull*)(smD + 23424);
    const int tid = threadIdx.x;
    const int hf = blockIdx.x;         // 0: prow 0..6, 1: prow 7..12
    const int pair = blockIdx.y;
    const int ir0 = 14 * hf;
    const int nr = 16 - 2 * hf;        // rows loaded: 16 / 14

    for (int i = tid; i < 2916; i += 512) { float w = c4w[i]; w4p[i] = pk2(w, w); }
    if (tid < 18) b4s[tid] = c4b[tid];
    {
        int per_ci = nr * 14;  // ulonglong2 units per ci
        int total = 18 * per_ci;
        for (int i = tid; i < total; i += 512) {
            int ci = i / per_ci, rem = i - ci * per_ci;
            const ulonglong2* src = (const ulonglong2*)(g_zp + (size_t)pair * 14112 + ci * 784 + ir0 * 28);
            ((ulonglong2*)(zS + ci * 448))[rem] = src[rem];
        }
    }
    __syncthreads();

    // strips: rl(7 or 6) x cq(4) x oc(18); COLS=8 overlapping quarters (c0 = 6*cq)
    int nstrip = (hf ? 6 : 7) * 4 * 18;
    if (tid < nstrip) {
        int oc = tid % 18;
        int r2 = tid / 18;
        int cq = r2 % 4;
        int rl = r2 / 4;
        int c0 = cq * 6;

        ull acc[2][8];
#pragma unroll
        for (int r = 0; r < 2; r++)
#pragma unroll
            for (int j = 0; j < 8; j++) acc[r][j] = 0ull;

#pragma unroll 1
        for (int ci = 0; ci < 18; ci++)
            conv3x3_pair<8, true>(zS + ci * 448 + rl * 56 + c0, 28, w4p + (oc * 18 + ci) * 9, acc);

        float b = b4s[oc];
        int prow = 7 * hf + rl;
        float* f0 = g_feat + (size_t)(2 * pair) * 3042 + (oc * 13 + prow) * 13;
        float* f1 = f0 + 3042;
        int plo = cq ? 1 : 0;
#pragma unroll
        for (int pp = 0; pp < 4; pp++) {
            if (pp >= plo) {
                float2 a0 = upk2(acc[0][2 * pp]), a1 = upk2(acc[0][2 * pp + 1]);
                float2 b0 = upk2(acc[1][2 * pp]), b1 = upk2(acc[1][2 * pp + 1]);
                f0[3 * cq + pp] = 0.25f * (a0.x + a1.x + b0.x + b1.x) + b;
                f1[3 * cq + pp] = 0.25f * (a0.y + a1.y + b0.y + b1.y) + b;
            }
        }
    }
}

// ---------------- MLP + expert routing + softmax, 8 samples/CTA (R4 verbatim) ----------------
#define SMEM_M ((8 * 3076 + 64 * 132 + 8 * 66 + 512 + 64) * 4)

__global__ __launch_bounds__(512, 1) void k_mlp(const float* __restrict__ scores, const float* __restrict__ times,
                                                const int* __restrict__ agents,
                                                const float* __restrict__ l1w, const float* __restrict__ l1b,
                                                const float* __restrict__ l2w, const float* __restrict__ l2b,
                                                const float* __restrict__ agw, const float* __restrict__ agb,
                                                float* __restrict__ out) {
    extern __shared__ float smM[];
    float* featS = smM;                       // stride 3076 per sample
    float* wT = featS + 8 * 3076;             // 64 x 132
    float* h1S = wT + 64 * 132;               // stride 66
    float* h2S = h1S + 8 * 66;                // stride 64
    float* logS = h2S + 512;
    const int tid = threadIdx.x;
    const int sb = blockIdx.x * 8;

    for (int i = tid; i < 8 * 1521; i += 512) {
        int s = i / 1521;
        int r = i - s * 1521;
        ((float2*)(featS + s * 3076))[r] = ((const float2*)(g_feat + (size_t)(sb + s) * 3042))[r];
    }
    if (tid < 8) {
        featS[tid * 3076 + 3042] = scores[sb + tid];
        featS[tid * 3076 + 3043] = times[sb + tid];
    }
    if (tid >= 32 && tid < 288) {
        int j = tid - 32;                     // zero-pad k = 3044..3075
        featS[(j >> 5) * 3076 + 3044 + (j & 31)] = 0.f;
    }
    __syncthreads();

    const int s = tid & 7, o = tid >> 3;      // o 0..63; 8 lanes per o broadcast
    ull f0a = 0, f1a = 0, f2a = 0, f3a = 0;
#pragma unroll 1
    for (int kt = 0; kt < 24; kt++) {
        int k0 = kt << 7;
        for (int i = tid; i < 8192; i += 512) {
            int oo = i >> 7, kk = i & 127;
            int k = k0 + kk;
            wT[oo * 132 + kk] = (k < 3044) ? l1w[oo * 3044 + k] : 0.f;
        }
        __syncthreads();
        const ull* fr = (const ull*)(featS + s * 3076 + k0);
        const ull* wr = (const ull*)(wT + o * 132);
#pragma unroll
        for (int kk = 0; kk < 64; kk += 4) {
            ffma2(f0a, fr[kk], wr[kk]);
            ffma2(f1a, fr[kk + 1], wr[kk + 1]);
            ffma2(f2a, fr[kk + 2], wr[kk + 2]);
            ffma2(f3a, fr[kk + 3], wr[kk + 3]);
        }
        __syncthreads();
    }
    {
        float2 a = upk2(f0a), b = upk2(f1a), c = upk2(f2a), d = upk2(f3a);
        float acc = (a.x + a.y) + (b.x + b.y) + (c.x + c.y) + (d.x + d.y);
        h1S[s * 66 + o] = tanhf(acc + l1b[o]);
    }
    __syncthreads();
    {
        const ull* hr = (const ull*)(h1S + s * 66);
        const ull* w2 = (const ull*)(l2w + o * 64);
        ull a0 = 0, a1 = 0;
#pragma unroll
        for (int kk = 0; kk < 32; kk += 2) {
            ffma2(a0, hr[kk], w2[kk]);
            ffma2(a1, hr[kk + 1], w2[kk + 1]);
        }
        float2 a = upk2(a0), b = upk2(a1);
        h2S[s * 64 + o] = tanhf(a.x + a.y + b.x + b.y + l2b[o]);
    }
    __syncthreads();
    if (tid < 40) {
        int ss = tid / 5, oo = tid - ss * 5;
        int ag = agents[sb + ss];
        const float* W = agw + (ag * 5 + oo) * 64;
        const float* h = h2S + ss * 64;
        float a = agb[ag * 5 + oo];
#pragma unroll
        for (int k = 0; k < 64; k++) a += W[k] * h[k];
        logS[ss * 8 + oo] = a;
    }
    __syncthreads();
    if (tid < 8) {
        float m = -1e30f;
        for (int i = 0; i < 5; i++) m = fmaxf(m, logS[tid * 8 + i]);
        float e[5], sum = 0.f;
        for (int i = 0; i < 5; i++) { e[i] = expf(logS[tid * 8 + i] - m); sum += e[i]; }
        float inv = 1.f / sum;
        for (int i = 0; i < 5; i++) out[(sb + tid) * 5 + i] = e[i] * inv;
    }
}

// ---------------- launch ----------------
extern "C" void kernel_launch(void* const* d_in, const int* in_sizes, int n_in,
                              void* d_out, int out_size) {
    const float* states = (const float*)d_in[0];
    const float* scores = (const float*)d_in[1];
    const float* times  = (const float*)d_in[2];
    const int*   agents = (const int*)d_in[3];
    const float* c1w = (const float*)d_in[4];
    const float* c1b = (const float*)d_in[5];
    const float* c2w = (const float*)d_in[6];
    const float* c2b = (const float*)d_in[7];
    const float* c3w = (const float*)d_in[8];
    const float* c3b = (const float*)d_in[9];
    const float* c4w = (const float*)d_in[10];
    const float* c4b = (const float*)d_in[11];
    const float* l1w = (const float*)d_in[12];
    const float* l1b = (const float*)d_in[13];
    const float* l2w = (const float*)d_in[14];
    const float* l2b = (const float*)d_in[15];
    const float* agw = (const float*)d_in[16];
    const float* agb = (const float*)d_in[17];
    float* out = (float*)d_out;

    cudaFuncSetAttribute(k_convA, cudaFuncAttributeMaxDynamicSharedMemorySize, SMEM_A);
    cudaFuncSetAttribute(k_conv3, cudaFuncAttributeMaxDynamicSharedMemorySize, SMEM_C3);
    cudaFuncSetAttribute(k_conv4, cudaFuncAttributeMaxDynamicSharedMemorySize, SMEM_C4);
    cudaFuncSetAttribute(k_mlp, cudaFuncAttributeMaxDynamicSharedMemorySize, SMEM_M);

    k_compose<<<3, 1024>>>(c1w, c1b, c2w, c2b);
    k_convA<<<dim3(6, 1024), 480, SMEM_A>>>(states);
    k_conv3<<<dim3(2, 1024), 512, SMEM_C3>>>(c3w, c3b);
    k_conv4<<<dim3(2, 1024), 512, SMEM_C4>>>(c4w, c4b);
    k_mlp<<<256, 512, SMEM_M>>>(scores, times, agents, l1w, l1b, l2w, l2b, agw, agb, out);
}

// round 11
// speedup vs baseline: 1.2266x; 1.0671x over previous
#include <cuda_runtime.h>
#include <math.h>

typedef unsigned long long ull;

#define NBATCH 2048
#define NPAIR 1024

// ---------------- device scratch ----------------
__device__ __align__(16) ull g_wA[2700];                             // composed 5x5 weights (w,w) pairs
__device__ float g_b2[18];                                           // composed bias
__device__ __align__(16) ull g_pool1p[(size_t)NPAIR * 18 * 30 * 30]; // pool1, sample-pair interleaved
__device__ __align__(16) ull g_zp[(size_t)NPAIR * 18 * 28 * 28];     // conv3 out, interleaved
__device__ __align__(16) float g_feat[(size_t)NBATCH * 3042];        // flattened features

// ---------------- packed f32x2 helpers ----------------
__device__ __forceinline__ void ffma2(ull& d, ull a, ull b) {
    asm("fma.rn.f32x2 %0, %1, %2, %0;" : "+l"(d) : "l"(a), "l"(b));
}
__device__ __forceinline__ ull pk2(float lo, float hi) {
    ull r;
    asm("mov.b64 %0, {%1, %2};" : "=l"(r) : "f"(lo), "f"(hi));
    return r;
}
__device__ __forceinline__ float2 upk2(ull v) {
    float2 r;
    asm("mov.b64 {%0, %1}, %2;" : "=f"(r.x), "=f"(r.y) : "l"(v));
    return r;
}

// ---------------- compose conv1*conv2 -> one 5x5 conv ----------------
__global__ void k_compose(const float* __restrict__ c1w, const float* __restrict__ c1b,
                          const float* __restrict__ c2w, const float* __restrict__ c2b) {
    int idx = blockIdx.x * blockDim.x + threadIdx.x;
    if (idx < 2700) {
        int o = idx / 150;
        int ci = (idx / 25) % 6;
        int y = (idx % 25) / 5;
        int x = idx % 5;
        int ky_lo = y > 2 ? y - 2 : 0, ky_hi = y < 2 ? y : 2;
        int kx_lo = x > 2 ? x - 2 : 0, kx_hi = x < 2 ? x : 2;
        float s = 0.f;
        for (int m = 0; m < 18; m++)
            for (int ky = ky_lo; ky <= ky_hi; ky++)
                for (int kx = kx_lo; kx <= kx_hi; kx++)
                    s += c1w[((m * 6 + ci) * 3 + ky) * 3 + kx] *
                         c2w[((o * 18 + m) * 3 + (y - ky)) * 3 + (x - kx)];
        g_wA[idx] = pk2(s, s);
    } else if (idx < 2718) {
        int o = idx - 2700;
        float s = c2b[o];
        for (int m = 0; m < 18; m++) {
            float t = 0.f;
            for (int q = 0; q < 9; q++) t += c2w[(o * 18 + m) * 9 + q];
            s += c1b[m] * t;
        }
        g_b2[o] = s;
    }
}

// ---------------- convA (R4 verbatim): composed 5x5 (6->18) + maxpool2 ----------------
// grid (5 rowbands, 1024 pairs), 512 thr, 2 CTAs/SM
// smem: W2ps 21600 | b2s 96 | inP 6*16*64 ull = 49152  => 70848
#define SMEM_A 70848

__global__ __launch_bounds__(512, 2) void k_convA(const float* __restrict__ states) {
    extern __shared__ char smA[];
    ull* W2ps = (ull*)smA;
    float* b2s = (float*)(smA + 21600);
    ull* inP = (ull*)(smA + 21696);
    const int tid = threadIdx.x;
    const int band = blockIdx.x;       // 0..4, 6 pooled rows each
    const int pair = blockIdx.y;
    const int ir0 = 12 * band;         // first input row of this band (16 rows used)

    for (int i = tid; i < 2700; i += 512) W2ps[i] = g_wA[i];
    if (tid < 18) b2s[tid] = g_b2[tid];
    {
        const float4* s0 = (const float4*)(states) + (size_t)pair * 12288;
        for (int i = tid; i < 1536; i += 512) {
            int c4 = i & 15, r = (i >> 4) & 15, ci = i >> 8;
            int goff = (ci * 64 + ir0 + r) * 16 + c4;
            float4 a = s0[goff], b = s0[goff + 6144];
            ull* d = inP + (ci << 10) + (r << 6) + (c4 << 2);
            d[0] = pk2(a.x, b.x); d[1] = pk2(a.y, b.y);
            d[2] = pk2(a.z, b.z); d[3] = pk2(a.w, b.w);
        }
    }
    __syncthreads();

    // strips: pl(6) x blk(10) x oc(18) = 1080; oc fastest (warp-broadcast data LDS)
    for (int t = tid; t < 1080; t += 512) {
        int oc = t % 18;
        int r2 = t / 18;
        int blk = r2 % 10;
        int pl = r2 / 10;          // local pooled row 0..5
        int c0 = blk * 6;

        ull acc[2][6];
#pragma unroll
        for (int r = 0; r < 2; r++)
#pragma unroll
            for (int j = 0; j < 6; j++) acc[r][j] = 0ull;

#pragma unroll 1
        for (int ci = 0; ci < 6; ci++) {
            const ull* rb = inP + (ci << 10) + (pl << 7) + c0;   // 2*pl*64 = pl<<7
            const ull* wc = W2ps + oc * 150 + ci * 25;
#pragma unroll
            for (int iy = 0; iy < 6; iy++) {
                ull v[10];
                {
                    const ull* vp = rb + (iy << 6);
#pragma unroll
                    for (int j = 0; j < 10; j++) v[j] = vp[j];
                }
                if (iy < 5) {
#pragma unroll
                    for (int kx = 0; kx < 5; kx++) {
                        ull w = wc[iy * 5 + kx];
#pragma unroll
                        for (int j = 0; j < 6; j++) ffma2(acc[0][j], w, v[j + kx]);
                    }
                }
                if (iy >= 1) {
#pragma unroll
                    for (int kx = 0; kx < 5; kx++) {
                        ull w = wc[(iy - 1) * 5 + kx];
#pragma unroll
                        for (int j = 0; j < 6; j++) ffma2(acc[1][j], w, v[j + kx]);
                    }
                }
            }
        }
        float bias = b2s[oc];
        int prow = band * 6 + pl;
        ull* op = g_pool1p + (((size_t)pair * 18 + oc) * 30 + prow) * 30 + blk * 3;
#pragma unroll
        for (int p = 0; p < 3; p++) {
            float2 a0 = upk2(acc[0][2 * p]), a1 = upk2(acc[0][2 * p + 1]);
            float2 b0 = upk2(acc[1][2 * p]), b1 = upk2(acc[1][2 * p + 1]);
            float2 m;
            m.x = fmaxf(fmaxf(a0.x, a1.x), fmaxf(b0.x, b1.x)) + bias;
            m.y = fmaxf(fmaxf(a0.y, a1.y), fmaxf(b0.y, b1.y)) + bias;
            ((float2*)op)[p] = m;
        }
    }
}

// ---------------- 3x3 pair-conv strip (rolling weight rows, strided weight layout) ----------------
// WSTRIDE: distance (in ull) between consecutive weight taps. 18 for [ci][k][oc] layout
// (lane-adjacent ocs read contiguous smem -> conflict-free weight LDS).
template <int COLS, bool ALIGNED, int WSTRIDE>
__device__ __forceinline__ void conv3x3_pair(const ull* rb, int rstride, const ull* wc,
                                             ull (&acc)[2][COLS]) {
    ull wn0 = 0, wn1 = 0, wn2 = 0, wp0 = 0, wp1 = 0, wp2 = 0;
#pragma unroll
    for (int iy = 0; iy < 4; iy++) {
        ull v[COLS + 2];
        if (ALIGNED) {
            const ulonglong2* vp = (const ulonglong2*)(rb + iy * rstride);
#pragma unroll
            for (int j = 0; j < (COLS + 2) / 2; j++) { ulonglong2 q = vp[j]; v[2 * j] = q.x; v[2 * j + 1] = q.y; }
        } else {
#pragma unroll
            for (int j = 0; j < COLS + 2; j++) v[j] = rb[iy * rstride + j];
        }
        if (iy < 3) {
            wn0 = wc[(iy * 3) * WSTRIDE];
            wn1 = wc[(iy * 3 + 1) * WSTRIDE];
            wn2 = wc[(iy * 3 + 2) * WSTRIDE];
#pragma unroll
            for (int j = 0; j < COLS; j++) {
                ffma2(acc[0][j], wn0, v[j]);
                ffma2(acc[0][j], wn1, v[j + 1]);
                ffma2(acc[0][j], wn2, v[j + 2]);
            }
        }
        if (iy >= 1) {
#pragma unroll
            for (int j = 0; j < COLS; j++) {
                ffma2(acc[1][j], wp0, v[j]);
                ffma2(acc[1][j], wp1, v[j + 1]);
                ffma2(acc[1][j], wp2, v[j + 2]);
            }
        }
        wp0 = wn0; wp1 = wn1; wp2 = wn2;
    }
}

// ---------------- conv3: 18->18, 30x30 -> 28x28 (R4 + transposed weights) ----------------
// grid (2 rowhalves, 1024 pairs), 512 thr, 2 CTAs/SM
// smem: w3p 23328 | b3 96 | pS 18*16*32 ull = 73728  => 97152
#define SMEM_C3 97152

__global__ __launch_bounds__(512, 2) void k_conv3(const float* __restrict__ c3w, const float* __restrict__ c3b) {
    extern __shared__ char smC[];
    ull* w3p = (ull*)smC;                 // layout [ci*9+k][oc] = [r*18 + oc]
    float* b3s = (float*)(smC + 23328);
    ull* pS = (ull*)(smC + 23424);
    const int tid = threadIdx.x;
    const int hf = blockIdx.x;         // 0: rowp 0..6, 1: rowp 7..13
    const int pair = blockIdx.y;
    const int ir0 = 14 * hf;

    for (int i = tid; i < 2916; i += 512) {
        int oc = i / 162, r = i - oc * 162;   // r = ci*9 + k
        float w = c3w[i];
        w3p[r * 18 + oc] = pk2(w, w);
    }
    if (tid < 18) b3s[tid] = c3b[tid];
    {
        const ull* src = g_pool1p + (size_t)pair * 16200;
        for (int e = tid; e < 8640; e += 512) {
            int c = e % 30;
            int r = (e / 30) & 15;
            int ci = e / 480;
            pS[ci * 512 + r * 32 + c] = src[(ci * 30 + ir0 + r) * 30 + c];
        }
    }
    __syncthreads();

    // strips: rl(7) x cq(4) x oc(18) = 504
    if (tid < 504) {
        int oc = tid % 18;
        int r2 = tid / 18;
        int cq = r2 % 4;
        int rl = r2 / 4;
        int c0 = cq * 7;

        ull acc[2][7];
#pragma unroll
        for (int r = 0; r < 2; r++)
#pragma unroll
            for (int j = 0; j < 7; j++) acc[r][j] = 0ull;

#pragma unroll 1
        for (int ci = 0; ci < 18; ci++)
            conv3x3_pair<7, false, 18>(pS + ci * 512 + rl * 64 + c0, 32, w3p + ci * 162 + oc, acc);

        float b = b3s[oc];
        int orow = 2 * (7 * hf + rl);
        ull* zb = g_zp + (((size_t)pair * 18 + oc) * 28 + orow) * 28 + c0;
#pragma unroll
        for (int r = 0; r < 2; r++)
#pragma unroll
            for (int j = 0; j < 7; j++) {
                float2 vv = upk2(acc[r][j]);
                ((float2*)zb)[r * 28 + j] = make_float2(vv.x + b, vv.y + b);
            }
    }
}

// ---------------- conv4: 18->18, 28x28 -> 26x26 + avgpool -> 13x13 (R4 + transposed weights) ----------------
// grid (2 rowhalves, 1024 pairs), 512 thr, 2 CTAs/SM
// smem: w4p 23328 | b4 96 | zS 18*16*28 ull = 64512  => 87936
#define SMEM_C4 87936

__global__ __launch_bounds__(512, 2) void k_conv4(const float* __restrict__ c4w, const float* __restrict__ c4b) {
    extern __shared__ char smD[];
    ull* w4p = (ull*)smD;                 // layout [ci*9+k][oc]
    float* b4s = (float*)(smD + 23328);
    ull* zS = (ull*)(smD + 23424);
    const int tid = threadIdx.x;
    const int hf = blockIdx.x;         // 0: prow 0..6, 1: prow 7..12
    const int pair = blockIdx.y;
    const int ir0 = 14 * hf;
    const int nr = 16 - 2 * hf;        // rows loaded: 16 / 14

    for (int i = tid; i < 2916; i += 512) {
        int oc = i / 162, r = i - oc * 162;
        float w = c4w[i];
        w4p[r * 18 + oc] = pk2(w, w);
    }
    if (tid < 18) b4s[tid] = c4b[tid];
    {
        int per_ci = nr * 14;  // ulonglong2 units per ci
        int total = 18 * per_ci;
        for (int i = tid; i < total; i += 512) {
            int ci = i / per_ci, rem = i - ci * per_ci;
            const ulonglong2* src = (const ulonglong2*)(g_zp + (size_t)pair * 14112 + ci * 784 + ir0 * 28);
            ((ulonglong2*)(zS + ci * 448))[rem] = src[rem];
        }
    }
    __syncthreads();

    // strips: rl(7 or 6) x cq(4) x oc(18); COLS=8 overlapping quarters (c0 = 6*cq)
    int nstrip = (hf ? 6 : 7) * 4 * 18;
    if (tid < nstrip) {
        int oc = tid % 18;
        int r2 = tid / 18;
        int cq = r2 % 4;
        int rl = r2 / 4;
        int c0 = cq * 6;

        ull acc[2][8];
#pragma unroll
        for (int r = 0; r < 2; r++)
#pragma unroll
            for (int j = 0; j < 8; j++) acc[r][j] = 0ull;

#pragma unroll 1
        for (int ci = 0; ci < 18; ci++)
            conv3x3_pair<8, true, 18>(zS + ci * 448 + rl * 56 + c0, 28, w4p + ci * 162 + oc, acc);

        float b = b4s[oc];
        int prow = 7 * hf + rl;
        float* f0 = g_feat + (size_t)(2 * pair) * 3042 + (oc * 13 + prow) * 13;
        float* f1 = f0 + 3042;
        int plo = cq ? 1 : 0;
#pragma unroll
        for (int pp = 0; pp < 4; pp++) {
            if (pp >= plo) {
                float2 a0 = upk2(acc[0][2 * pp]), a1 = upk2(acc[0][2 * pp + 1]);
                float2 b0 = upk2(acc[1][2 * pp]), b1 = upk2(acc[1][2 * pp + 1]);
                f0[3 * cq + pp] = 0.25f * (a0.x + a1.x + b0.x + b1.x) + b;
                f1[3 * cq + pp] = 0.25f * (a0.y + a1.y + b0.y + b1.y) + b;
            }
        }
    }
}

// ---------------- MLP + expert routing + softmax, 8 samples/CTA (R4 verbatim) ----------------
#define SMEM_M ((8 * 3076 + 64 * 132 + 8 * 66 + 512 + 64) * 4)

__global__ __launch_bounds__(512, 1) void k_mlp(const float* __restrict__ scores, const float* __restrict__ times,
                                                const int* __restrict__ agents,
                                                const float* __restrict__ l1w, const float* __restrict__ l1b,
                                                const float* __restrict__ l2w, const float* __restrict__ l2b,
                                                const float* __restrict__ agw, const float* __restrict__ agb,
                                                float* __restrict__ out) {
    extern __shared__ float smM[];
    float* featS = smM;                       // stride 3076 per sample
    float* wT = featS + 8 * 3076;             // 64 x 132
    float* h1S = wT + 64 * 132;               // stride 66
    float* h2S = h1S + 8 * 66;                // stride 64
    float* logS = h2S + 512;
    const int tid = threadIdx.x;
    const int sb = blockIdx.x * 8;

    for (int i = tid; i < 8 * 1521; i += 512) {
        int s = i / 1521;
        int r = i - s * 1521;
        ((float2*)(featS + s * 3076))[r] = ((const float2*)(g_feat + (size_t)(sb + s) * 3042))[r];
    }
    if (tid < 8) {
        featS[tid * 3076 + 3042] = scores[sb + tid];
        featS[tid * 3076 + 3043] = times[sb + tid];
    }
    if (tid >= 32 && tid < 288) {
        int j = tid - 32;                     // zero-pad k = 3044..3075
        featS[(j >> 5) * 3076 + 3044 + (j & 31)] = 0.f;
    }
    __syncthreads();

    const int s = tid & 7, o = tid >> 3;      // o 0..63; 8 lanes per o broadcast
    ull f0a = 0, f1a = 0, f2a = 0, f3a = 0;
#pragma unroll 1
    for (int kt = 0; kt < 24; kt++) {
        int k0 = kt << 7;
        for (int i = tid; i < 8192; i += 512) {
            int oo = i >> 7, kk = i & 127;
            int k = k0 + kk;
            wT[oo * 132 + kk] = (k < 3044) ? l1w[oo * 3044 + k] : 0.f;
        }
        __syncthreads();
        const ull* fr = (const ull*)(featS + s * 3076 + k0);
        const ull* wr = (const ull*)(wT + o * 132);
#pragma unroll
        for (int kk = 0; kk < 64; kk += 4) {
            ffma2(f0a, fr[kk], wr[kk]);
            ffma2(f1a, fr[kk + 1], wr[kk + 1]);
            ffma2(f2a, fr[kk + 2], wr[kk + 2]);
            ffma2(f3a, fr[kk + 3], wr[kk + 3]);
        }
        __syncthreads();
    }
    {
        float2 a = upk2(f0a), b = upk2(f1a), c = upk2(f2a), d = upk2(f3a);
        float acc = (a.x + a.y) + (b.x + b.y) + (c.x + c.y) + (d.x + d.y);
        h1S[s * 66 + o] = tanhf(acc + l1b[o]);
    }
    __syncthreads();
    {
        const ull* hr = (const ull*)(h1S + s * 66);
        const ull* w2 = (const ull*)(l2w + o * 64);
        ull a0 = 0, a1 = 0;
#pragma unroll
        for (int kk = 0; kk < 32; kk += 2) {
            ffma2(a0, hr[kk], w2[kk]);
            ffma2(a1, hr[kk + 1], w2[kk + 1]);
        }
        float2 a = upk2(a0), b = upk2(a1);
        h2S[s * 64 + o] = tanhf(a.x + a.y + b.x + b.y + l2b[o]);
    }
    __syncthreads();
    if (tid < 40) {
        int ss = tid / 5, oo = tid - ss * 5;
        int ag = agents[sb + ss];
        const float* W = agw + (ag * 5 + oo) * 64;
        const float* h = h2S + ss * 64;
        float a = agb[ag * 5 + oo];
#pragma unroll
        for (int k = 0; k < 64; k++) a += W[k] * h[k];
        logS[ss * 8 + oo] = a;
    }
    __syncthreads();
    if (tid < 8) {
        float m = -1e30f;
        for (int i = 0; i < 5; i++) m = fmaxf(m, logS[tid * 8 + i]);
        float e[5], sum = 0.f;
        for (int i = 0; i < 5; i++) { e[i] = expf(logS[tid * 8 + i] - m); sum += e[i]; }
        float inv = 1.f / sum;
        for (int i = 0; i < 5; i++) out[(sb + tid) * 5 + i] = e[i] * inv;
    }
}

// ---------------- launch ----------------
extern "C" void kernel_launch(void* const* d_in, const int* in_sizes, int n_in,
                              void* d_out, int out_size) {
    const float* states = (const float*)d_in[0];
    const float* scores = (const float*)d_in[1];
    const float* times  = (const float*)d_in[2];
    const int*   agents = (const int*)d_in[3];
    const float* c1w = (const float*)d_in[4];
    const float* c1b = (const float*)d_in[5];
    const float* c2w = (const float*)d_in[6];
    const float* c2b = (const float*)d_in[7];
    const float* c3w = (const float*)d_in[8];
    const float* c3b = (const float*)d_in[9];
    const float* c4w = (const float*)d_in[10];
    const float* c4b = (const float*)d_in[11];
    const float* l1w = (const float*)d_in[12];
    const float* l1b = (const float*)d_in[13];
    const float* l2w = (const float*)d_in[14];
    const float* l2b = (const float*)d_in[15];
    const float* agw = (const float*)d_in[16];
    const float* agb = (const float*)d_in[17];
    float* out = (float*)d_out;

    cudaFuncSetAttribute(k_convA, cudaFuncAttributeMaxDynamicSharedMemorySize, SMEM_A);
    cudaFuncSetAttribute(k_conv3, cudaFuncAttributeMaxDynamicSharedMemorySize, SMEM_C3);
    cudaFuncSetAttribute(k_conv4, cudaFuncAttributeMaxDynamicSharedMemorySize, SMEM_C4);
    cudaFuncSetAttribute(k_mlp, cudaFuncAttributeMaxDynamicSharedMemorySize, SMEM_M);

    k_compose<<<3, 1024>>>(c1w, c1b, c2w, c2b);
    k_convA<<<dim3(5, 1024), 512, SMEM_A>>>(states);
    k_conv3<<<dim3(2, 1024), 512, SMEM_C3>>>(c3w, c3b);
    k_conv4<<<dim3(2, 1024), 512, SMEM_C4>>>(c4w, c4b);
    k_mlp<<<256, 512, SMEM_M>>>(scores, times, agents, l1w, l1b, l2w, l2b, agw, agb, out);
}

// round 12
// speedup vs baseline: 1.2333x; 1.0054x over previous
#include <cuda_runtime.h>
#include <math.h>

typedef unsigned long long ull;

#define NBATCH 2048
#define NPAIR 1024

// ---------------- device scratch ----------------
__device__ __align__(16) ull g_wAt[2700];                            // composed 5x5 weights, transposed [ci*25+k][oc], (w,w) pairs
__device__ float g_b2[18];                                           // composed bias
__device__ __align__(16) ull g_w4c[5184];                            // composed conv4+avgpool 4x4 weights, [ci*16+u*4+v][oc]
__device__ __align__(16) ull g_pool1p[(size_t)NPAIR * 18 * 30 * 30]; // pool1, sample-pair interleaved
__device__ __align__(16) ull g_zp[(size_t)NPAIR * 18 * 28 * 28];     // conv3 out, interleaved
__device__ __align__(16) float g_feat[(size_t)NBATCH * 3042];        // flattened features

// ---------------- packed f32x2 helpers ----------------
__device__ __forceinline__ void ffma2(ull& d, ull a, ull b) {
    asm("fma.rn.f32x2 %0, %1, %2, %0;" : "+l"(d) : "l"(a), "l"(b));
}
__device__ __forceinline__ ull pk2(float lo, float hi) {
    ull r;
    asm("mov.b64 %0, {%1, %2};" : "=l"(r) : "f"(lo), "f"(hi));
    return r;
}
__device__ __forceinline__ float2 upk2(ull v) {
    float2 r;
    asm("mov.b64 {%0, %1}, %2;" : "=f"(r.x), "=f"(r.y) : "l"(v));
    return r;
}

// ---------------- compose conv1*conv2 -> one 5x5 conv (transposed store) ----------------
__global__ void k_compose(const float* __restrict__ c1w, const float* __restrict__ c1b,
                          const float* __restrict__ c2w, const float* __restrict__ c2b) {
    int idx = blockIdx.x * blockDim.x + threadIdx.x;
    if (idx < 2700) {
        int o = idx / 150;
        int r = idx - o * 150;          // r = ci*25 + y*5 + x
        int ci = r / 25;
        int y = (r % 25) / 5;
        int x = r % 5;
        int ky_lo = y > 2 ? y - 2 : 0, ky_hi = y < 2 ? y : 2;
        int kx_lo = x > 2 ? x - 2 : 0, kx_hi = x < 2 ? x : 2;
        float s = 0.f;
        for (int m = 0; m < 18; m++)
            for (int ky = ky_lo; ky <= ky_hi; ky++)
                for (int kx = kx_lo; kx <= kx_hi; kx++)
                    s += c1w[((m * 6 + ci) * 3 + ky) * 3 + kx] *
                         c2w[((o * 18 + m) * 3 + (y - ky)) * 3 + (x - kx)];
        g_wAt[r * 18 + o] = pk2(s, s);
    } else if (idx < 2718) {
        int o = idx - 2700;
        float s = c2b[o];
        for (int m = 0; m < 18; m++) {
            float t = 0.f;
            for (int q = 0; q < 9; q++) t += c2w[(o * 18 + m) * 9 + q];
            s += c1b[m] * t;
        }
        g_b2[o] = s;
    }
}

// ---------------- compose conv4*avgpool -> 4x4 stride-2 conv ----------------
__global__ void k_packw4c(const float* __restrict__ c4w) {
    int idx = blockIdx.x * blockDim.x + threadIdx.x;   // over 18*18*16
    if (idx < 5184) {
        int oc = idx / 288;
        int rem = idx - oc * 288;
        int ci = rem / 16;
        int u = (rem % 16) / 4;
        int v = rem % 4;
        float s = 0.f;
        for (int a = 0; a < 2; a++) {
            int ky = u - a;
            if (ky < 0 || ky > 2) continue;
            for (int b = 0; b < 2; b++) {
                int kx = v - b;
                if (kx < 0 || kx > 2) continue;
                s += c4w[((oc * 18 + ci) * 3 + ky) * 3 + kx];
            }
        }
        s *= 0.25f;
        g_w4c[(ci * 16 + u * 4 + v) * 18 + oc] = pk2(s, s);
    }
}

// ---------------- convA: composed 5x5 (6->18) + maxpool2 — rolling transposed weights ----------------
// grid (5 rowbands, 1024 pairs), 512 thr, 2 CTAs/SM
// smem: wAts 21600 | b2s 96 | inP 6*16*64 ull = 49152  => 70848
#define SMEM_A 70848

__global__ __launch_bounds__(512, 2) void k_convA(const float* __restrict__ states) {
    extern __shared__ char smA[];
    ull* wAts = (ull*)smA;              // [ci*25+k][oc]
    float* b2s = (float*)(smA + 21600);
    ull* inP = (ull*)(smA + 21696);
    const int tid = threadIdx.x;
    const int band = blockIdx.x;        // 0..4, 6 pooled rows each
    const int pair = blockIdx.y;
    const int ir0 = 12 * band;

    for (int i = tid; i < 2700; i += 512) wAts[i] = g_wAt[i];
    if (tid < 18) b2s[tid] = g_b2[tid];
    {
        const float4* s0 = (const float4*)(states) + (size_t)pair * 12288;
        for (int i = tid; i < 1536; i += 512) {
            int c4 = i & 15, r = (i >> 4) & 15, ci = i >> 8;
            int goff = (ci * 64 + ir0 + r) * 16 + c4;
            float4 a = s0[goff], b = s0[goff + 6144];
            ull* d = inP + (ci << 10) + (r << 6) + (c4 << 2);
            d[0] = pk2(a.x, b.x); d[1] = pk2(a.y, b.y);
            d[2] = pk2(a.z, b.z); d[3] = pk2(a.w, b.w);
        }
    }
    __syncthreads();

    // strips: pl(6) x blk(15) x oc(18) = 1620; oc fastest
    for (int t = tid; t < 1620; t += 512) {
        int oc = t % 18;
        int r2 = t / 18;
        int blk = r2 % 15;
        int pl = r2 / 15;           // local pooled row 0..5
        int c0 = blk * 4;           // conv col base (4 cols per strip)

        ull acc[2][4];
#pragma unroll
        for (int r = 0; r < 2; r++)
#pragma unroll
            for (int j = 0; j < 4; j++) acc[r][j] = 0ull;

#pragma unroll 1
        for (int ci = 0; ci < 6; ci++) {
            const ull* rb = inP + (ci << 10) + (pl << 7) + c0;
            const ull* wb = wAts + ci * 450 + oc;   // (ci*25)*18 + oc
            ull wn0 = 0, wn1 = 0, wn2 = 0, wn3 = 0, wn4 = 0;
            ull wp0 = 0, wp1 = 0, wp2 = 0, wp3 = 0, wp4 = 0;
#pragma unroll
            for (int iy = 0; iy < 6; iy++) {
                ull v[8];
                {
                    const ulonglong2* vp = (const ulonglong2*)(rb + (iy << 6));
#pragma unroll
                    for (int j = 0; j < 4; j++) { ulonglong2 q = vp[j]; v[2 * j] = q.x; v[2 * j + 1] = q.y; }
                }
                if (iy < 5) {
                    wn0 = wb[(iy * 5) * 18];
                    wn1 = wb[(iy * 5 + 1) * 18];
                    wn2 = wb[(iy * 5 + 2) * 18];
                    wn3 = wb[(iy * 5 + 3) * 18];
                    wn4 = wb[(iy * 5 + 4) * 18];
#pragma unroll
                    for (int j = 0; j < 4; j++) {
                        ffma2(acc[0][j], wn0, v[j]);
                        ffma2(acc[0][j], wn1, v[j + 1]);
                        ffma2(acc[0][j], wn2, v[j + 2]);
                        ffma2(acc[0][j], wn3, v[j + 3]);
                        ffma2(acc[0][j], wn4, v[j + 4]);
                    }
                }
                if (iy >= 1) {
#pragma unroll
                    for (int j = 0; j < 4; j++) {
                        ffma2(acc[1][j], wp0, v[j]);
                        ffma2(acc[1][j], wp1, v[j + 1]);
                        ffma2(acc[1][j], wp2, v[j + 2]);
                        ffma2(acc[1][j], wp3, v[j + 3]);
                        ffma2(acc[1][j], wp4, v[j + 4]);
                    }
                }
                wp0 = wn0; wp1 = wn1; wp2 = wn2; wp3 = wn3; wp4 = wn4;
            }
        }
        float bias = b2s[oc];
        int prow = band * 6 + pl;
        ull* op = g_pool1p + (((size_t)pair * 18 + oc) * 30 + prow) * 30 + blk * 2;
#pragma unroll
        for (int p = 0; p < 2; p++) {
            float2 a0 = upk2(acc[0][2 * p]), a1 = upk2(acc[0][2 * p + 1]);
            float2 b0 = upk2(acc[1][2 * p]), b1 = upk2(acc[1][2 * p + 1]);
            float mx = fmaxf(fmaxf(a0.x, a1.x), fmaxf(b0.x, b1.x)) + bias;
            float my = fmaxf(fmaxf(a0.y, a1.y), fmaxf(b0.y, b1.y)) + bias;
            op[p] = pk2(mx, my);
        }
    }
}

// ---------------- 3x3 pair-conv strip (rolling weight rows, strided weight layout) ----------------
template <int COLS, bool ALIGNED, int WSTRIDE>
__device__ __forceinline__ void conv3x3_pair(const ull* rb, int rstride, const ull* wc,
                                             ull (&acc)[2][COLS]) {
    ull wn0 = 0, wn1 = 0, wn2 = 0, wp0 = 0, wp1 = 0, wp2 = 0;
#pragma unroll
    for (int iy = 0; iy < 4; iy++) {
        ull v[COLS + 2];
        if (ALIGNED) {
            const ulonglong2* vp = (const ulonglong2*)(rb + iy * rstride);
#pragma unroll
            for (int j = 0; j < (COLS + 2) / 2; j++) { ulonglong2 q = vp[j]; v[2 * j] = q.x; v[2 * j + 1] = q.y; }
        } else {
#pragma unroll
            for (int j = 0; j < COLS + 2; j++) v[j] = rb[iy * rstride + j];
        }
        if (iy < 3) {
            wn0 = wc[(iy * 3) * WSTRIDE];
            wn1 = wc[(iy * 3 + 1) * WSTRIDE];
            wn2 = wc[(iy * 3 + 2) * WSTRIDE];
#pragma unroll
            for (int j = 0; j < COLS; j++) {
                ffma2(acc[0][j], wn0, v[j]);
                ffma2(acc[0][j], wn1, v[j + 1]);
                ffma2(acc[0][j], wn2, v[j + 2]);
            }
        }
        if (iy >= 1) {
#pragma unroll
            for (int j = 0; j < COLS; j++) {
                ffma2(acc[1][j], wp0, v[j]);
                ffma2(acc[1][j], wp1, v[j + 1]);
                ffma2(acc[1][j], wp2, v[j + 2]);
            }
        }
        wp0 = wn0; wp1 = wn1; wp2 = wn2;
    }
}

// ---------------- conv3 (R11 verbatim): 18->18, 30x30 -> 28x28 ----------------
// grid (2 rowhalves, 1024 pairs), 512 thr, 2 CTAs/SM
// smem: w3p 23328 | b3 96 | pS 18*16*32 ull = 73728  => 97152
#define SMEM_C3 97152

__global__ __launch_bounds__(512, 2) void k_conv3(const float* __restrict__ c3w, const float* __restrict__ c3b) {
    extern __shared__ char smC[];
    ull* w3p = (ull*)smC;                 // layout [ci*9+k][oc]
    float* b3s = (float*)(smC + 23328);
    ull* pS = (ull*)(smC + 23424);
    const int tid = threadIdx.x;
    const int hf = blockIdx.x;
    const int pair = blockIdx.y;
    const int ir0 = 14 * hf;

    for (int i = tid; i < 2916; i += 512) {
        int oc = i / 162, r = i - oc * 162;
        float w = c3w[i];
        w3p[r * 18 + oc] = pk2(w, w);
    }
    if (tid < 18) b3s[tid] = c3b[tid];
    {
        const ull* src = g_pool1p + (size_t)pair * 16200;
        for (int e = tid; e < 8640; e += 512) {
            int c = e % 30;
            int r = (e / 30) & 15;
            int ci = e / 480;
            pS[ci * 512 + r * 32 + c] = src[(ci * 30 + ir0 + r) * 30 + c];
        }
    }
    __syncthreads();

    if (tid < 504) {
        int oc = tid % 18;
        int r2 = tid / 18;
        int cq = r2 % 4;
        int rl = r2 / 4;
        int c0 = cq * 7;

        ull acc[2][7];
#pragma unroll
        for (int r = 0; r < 2; r++)
#pragma unroll
            for (int j = 0; j < 7; j++) acc[r][j] = 0ull;

#pragma unroll 1
        for (int ci = 0; ci < 18; ci++)
            conv3x3_pair<7, false, 18>(pS + ci * 512 + rl * 64 + c0, 32, w3p + ci * 162 + oc, acc);

        float b = b3s[oc];
        int orow = 2 * (7 * hf + rl);
        ull* zb = g_zp + (((size_t)pair * 18 + oc) * 28 + orow) * 28 + c0;
#pragma unroll
        for (int r = 0; r < 2; r++)
#pragma unroll
            for (int j = 0; j < 7; j++) {
                float2 vv = upk2(acc[r][j]);
                ((float2*)zb)[r * 28 + j] = make_float2(vv.x + b, vv.y + b);
            }
    }
}

// ---------------- conv4c: composed conv4+avgpool = 4x4 stride-2 conv, 28x28 -> 13x13 ----------------
// grid (2 rowhalves, 1024 pairs), 512 thr, 2 CTAs/SM
// smem: w4cs 41472 | b4 96 | zS 18*16*28 ull = 64512  => 106080
#define SMEM_C4 106080

__global__ __launch_bounds__(512, 2) void k_conv4c(const float* __restrict__ c4b) {
    extern __shared__ char smD[];
    ull* w4cs = (ull*)smD;                // [ci*16 + u*4 + v][oc]
    float* b4s = (float*)(smD + 41472);
    ull* zS = (ull*)(smD + 41568);
    const int tid = threadIdx.x;
    const int hf = blockIdx.x;            // 0: pr 0..6 (rows 0..15), 1: pr 7..12 (rows 14..27)
    const int pair = blockIdx.y;
    const int ir0 = 14 * hf;
    const int nr = 16 - 2 * hf;

    for (int i = tid; i < 5184; i += 512) w4cs[i] = g_w4c[i];
    if (tid < 18) b4s[tid] = c4b[tid];
    {
        int per_ci = nr * 14;  // ulonglong2 units per ci
        int total = 18 * per_ci;
        for (int i = tid; i < total; i += 512) {
            int ci = i / per_ci, rem = i - ci * per_ci;
            const ulonglong2* src = (const ulonglong2*)(g_zp + (size_t)pair * 14112 + ci * 784 + ir0 * 28);
            ((ulonglong2*)(zS + ci * 448))[rem] = src[rem];
        }
    }
    __syncthreads();

    // strips: pr_l x cq(4) x oc(18); pooled cols 3cq..3cq+3 (overlap col at cq>0)
    int nstrip = (hf ? 6 : 7) * 4 * 18;
    if (tid < nstrip) {
        int oc = tid % 18;
        int r2 = tid / 18;
        int cq = r2 % 4;
        int pr_l = r2 / 4;
        int c0 = cq * 6;   // input col base (ull); pooled base col 3cq

        ull acc[4];
#pragma unroll
        for (int j = 0; j < 4; j++) acc[j] = 0ull;

#pragma unroll 1
        for (int ci = 0; ci < 18; ci++) {
            const ull* rb = zS + ci * 448 + (2 * pr_l) * 28 + c0;
            const ull* wb = w4cs + ci * 288 + oc;   // (ci*16)*18 + oc
#pragma unroll
            for (int u = 0; u < 4; u++) {
                ull v[10];
                {
                    const ulonglong2* vp = (const ulonglong2*)(rb + u * 28);
#pragma unroll
                    for (int j = 0; j < 5; j++) { ulonglong2 q = vp[j]; v[2 * j] = q.x; v[2 * j + 1] = q.y; }
                }
                ull w0 = wb[(u * 4) * 18];
                ull w1 = wb[(u * 4 + 1) * 18];
                ull w2 = wb[(u * 4 + 2) * 18];
                ull w3 = wb[(u * 4 + 3) * 18];
#pragma unroll
                for (int pc = 0; pc < 4; pc++) {
                    ffma2(acc[pc], w0, v[2 * pc]);
                    ffma2(acc[pc], w1, v[2 * pc + 1]);
                    ffma2(acc[pc], w2, v[2 * pc + 2]);
                    ffma2(acc[pc], w3, v[2 * pc + 3]);
                }
            }
        }
        float b = b4s[oc];
        int pr = 7 * hf + pr_l;
        float* f0 = g_feat + (size_t)(2 * pair) * 3042 + (oc * 13 + pr) * 13 + 3 * cq;
        float* f1 = f0 + 3042;
        int plo = cq ? 1 : 0;
#pragma unroll
        for (int pp = 0; pp < 4; pp++) {
            if (pp >= plo) {
                float2 vv = upk2(acc[pp]);
                f0[pp] = vv.x + b;
                f1[pp] = vv.y + b;
            }
        }
    }
}

// ---------------- MLP + expert routing + softmax, 8 samples/CTA (R4 verbatim) ----------------
#define SMEM_M ((8 * 3076 + 64 * 132 + 8 * 66 + 512 + 64) * 4)

__global__ __launch_bounds__(512, 1) void k_mlp(const float* __restrict__ scores, const float* __restrict__ times,
                                                const int* __restrict__ agents,
                                                const float* __restrict__ l1w, const float* __restrict__ l1b,
                                                const float* __restrict__ l2w, const float* __restrict__ l2b,
                                                const float* __restrict__ agw, const float* __restrict__ agb,
                                                float* __restrict__ out) {
    extern __shared__ float smM[];
    float* featS = smM;
    float* wT = featS + 8 * 3076;
    float* h1S = wT + 64 * 132;
    float* h2S = h1S + 8 * 66;
    float* logS = h2S + 512;
    const int tid = threadIdx.x;
    const int sb = blockIdx.x * 8;

    for (int i = tid; i < 8 * 1521; i += 512) {
        int s = i / 1521;
        int r = i - s * 1521;
        ((float2*)(featS + s * 3076))[r] = ((const float2*)(g_feat + (size_t)(sb + s) * 3042))[r];
    }
    if (tid < 8) {
        featS[tid * 3076 + 3042] = scores[sb + tid];
        featS[tid * 3076 + 3043] = times[sb + tid];
    }
    if (tid >= 32 && tid < 288) {
        int j = tid - 32;
        featS[(j >> 5) * 3076 + 3044 + (j & 31)] = 0.f;
    }
    __syncthreads();

    const int s = tid & 7, o = tid >> 3;
    ull f0a = 0, f1a = 0, f2a = 0, f3a = 0;
#pragma unroll 1
    for (int kt = 0; kt < 24; kt++) {
        int k0 = kt << 7;
        for (int i = tid; i < 8192; i += 512) {
            int oo = i >> 7, kk = i & 127;
            int k = k0 + kk;
            wT[oo * 132 + kk] = (k < 3044) ? l1w[oo * 3044 + k] : 0.f;
        }
        __syncthreads();
        const ull* fr = (const ull*)(featS + s * 3076 + k0);
        const ull* wr = (const ull*)(wT + o * 132);
#pragma unroll
        for (int kk = 0; kk < 64; kk += 4) {
            ffma2(f0a, fr[kk], wr[kk]);
            ffma2(f1a, fr[kk + 1], wr[kk + 1]);
            ffma2(f2a, fr[kk + 2], wr[kk + 2]);
            ffma2(f3a, fr[kk + 3], wr[kk + 3]);
        }
        __syncthreads();
    }
    {
        float2 a = upk2(f0a), b = upk2(f1a), c = upk2(f2a), d = upk2(f3a);
        float acc = (a.x + a.y) + (b.x + b.y) + (c.x + c.y) + (d.x + d.y);
        h1S[s * 66 + o] = tanhf(acc + l1b[o]);
    }
    __syncthreads();
    {
        const ull* hr = (const ull*)(h1S + s * 66);
        const ull* w2 = (const ull*)(l2w + o * 64);
        ull a0 = 0, a1 = 0;
#pragma unroll
        for (int kk = 0; kk < 32; kk += 2) {
            ffma2(a0, hr[kk], w2[kk]);
            ffma2(a1, hr[kk + 1], w2[kk + 1]);
        }
        float2 a = upk2(a0), b = upk2(a1);
        h2S[s * 64 + o] = tanhf(a.x + a.y + b.x + b.y + l2b[o]);
    }
    __syncthreads();
    if (tid < 40) {
        int ss = tid / 5, oo = tid - ss * 5;
        int ag = agents[sb + ss];
        const float* W = agw + (ag * 5 + oo) * 64;
        const float* h = h2S + ss * 64;
        float a = agb[ag * 5 + oo];
#pragma unroll
        for (int k = 0; k < 64; k++) a += W[k] * h[k];
        logS[ss * 8 + oo] = a;
    }
    __syncthreads();
    if (tid < 8) {
        float m = -1e30f;
        for (int i = 0; i < 5; i++) m = fmaxf(m, logS[tid * 8 + i]);
        float e[5], sum = 0.f;
        for (int i = 0; i < 5; i++) { e[i] = expf(logS[tid * 8 + i] - m); sum += e[i]; }
        float inv = 1.f / sum;
        for (int i = 0; i < 5; i++) out[(sb + tid) * 5 + i] = e[i] * inv;
    }
}

// ---------------- launch ----------------
extern "C" void kernel_launch(void* const* d_in, const int* in_sizes, int n_in,
                              void* d_out, int out_size) {
    const float* states = (const float*)d_in[0];
    const float* scores = (const float*)d_in[1];
    const float* times  = (const float*)d_in[2];
    const int*   agents = (const int*)d_in[3];
    const float* c1w = (const float*)d_in[4];
    const float* c1b = (const float*)d_in[5];
    const float* c2w = (const float*)d_in[6];
    const float* c2b = (const float*)d_in[7];
    const float* c3w = (const float*)d_in[8];
    const float* c3b = (const float*)d_in[9];
    const float* c4w = (const float*)d_in[10];
    const float* c4b = (const float*)d_in[11];
    const float* l1w = (const float*)d_in[12];
    const float* l1b = (const float*)d_in[13];
    const float* l2w = (const float*)d_in[14];
    const float* l2b = (const float*)d_in[15];
    const float* agw = (const float*)d_in[16];
    const float* agb = (const float*)d_in[17];
    float* out = (float*)d_out;

    cudaFuncSetAttribute(k_convA, cudaFuncAttributeMaxDynamicSharedMemorySize, SMEM_A);
    cudaFuncSetAttribute(k_conv3, cudaFuncAttributeMaxDynamicSharedMemorySize, SMEM_C3);
    cudaFuncSetAttribute(k_conv4c, cudaFuncAttributeMaxDynamicSharedMemorySize, SMEM_C4);
    cudaFuncSetAttribute(k_mlp, cudaFuncAttributeMaxDynamicSharedMemorySize, SMEM_M);

    k_compose<<<3, 1024>>>(c1w, c1b, c2w, c2b);
    k_packw4c<<<11, 512>>>(c4w);
    k_convA<<<dim3(5, 1024), 512, SMEM_A>>>(states);
    k_conv3<<<dim3(2, 1024), 512, SMEM_C3>>>(c3w, c3b);
    k_conv4c<<<dim3(2, 1024), 512, SMEM_C4>>>(c4b);
    k_mlp<<<256, 512, SMEM_M>>>(scores, times, agents, l1w, l1b, l2w, l2b, agw, agb, out);
}

// round 13
// speedup vs baseline: 1.4727x; 1.1941x over previous
#include <cuda_runtime.h>
#include <math.h>

typedef unsigned long long ull;

#define NBATCH 2048
#define NPAIR 1024

// ---------------- device scratch ----------------
__device__ __align__(16) ull g_wAt[2700];                            // composed 5x5 conv1*conv2, transposed [ci*25+k][oc], (w,w) pairs
__device__ float g_b2[18];
__device__ __align__(16) float g_w34c[11664];                        // composed conv3*conv4*avgpool 6x6 stride2, [(ci*36+u*6+v)*18+oc]
__device__ float g_b34[18];
__device__ __align__(16) ull g_pool1p[(size_t)NPAIR * 18 * 30 * 30]; // pool1, sample-pair interleaved
__device__ __align__(16) float g_feat[(size_t)NBATCH * 3042];        // flattened features

// ---------------- packed f32x2 helpers ----------------
__device__ __forceinline__ void ffma2(ull& d, ull a, ull b) {
    asm("fma.rn.f32x2 %0, %1, %2, %0;" : "+l"(d) : "l"(a), "l"(b));
}
__device__ __forceinline__ ull pk2(float lo, float hi) {
    ull r;
    asm("mov.b64 %0, {%1, %2};" : "=l"(r) : "f"(lo), "f"(hi));
    return r;
}
__device__ __forceinline__ float2 upk2(ull v) {
    float2 r;
    asm("mov.b64 {%0, %1}, %2;" : "=f"(r.x), "=f"(r.y) : "l"(v));
    return r;
}

// ---------------- compose conv1*conv2 -> one 5x5 conv (transposed store) ----------------
__global__ void k_compose(const float* __restrict__ c1w, const float* __restrict__ c1b,
                          const float* __restrict__ c2w, const float* __restrict__ c2b) {
    int idx = blockIdx.x * blockDim.x + threadIdx.x;
    if (idx < 2700) {
        int o = idx / 150;
        int r = idx - o * 150;          // r = ci*25 + y*5 + x
        int ci = r / 25;
        int y = (r % 25) / 5;
        int x = r % 5;
        int ky_lo = y > 2 ? y - 2 : 0, ky_hi = y < 2 ? y : 2;
        int kx_lo = x > 2 ? x - 2 : 0, kx_hi = x < 2 ? x : 2;
        float s = 0.f;
        for (int m = 0; m < 18; m++)
            for (int ky = ky_lo; ky <= ky_hi; ky++)
                for (int kx = kx_lo; kx <= kx_hi; kx++)
                    s += c1w[((m * 6 + ci) * 3 + ky) * 3 + kx] *
                         c2w[((o * 18 + m) * 3 + (y - ky)) * 3 + (x - kx)];
        g_wAt[r * 18 + o] = pk2(s, s);
    } else if (idx < 2718) {
        int o = idx - 2700;
        float s = c2b[o];
        for (int m = 0; m < 18; m++) {
            float t = 0.f;
            for (int q = 0; q < 9; q++) t += c2w[(o * 18 + m) * 9 + q];
            s += c1b[m] * t;
        }
        g_b2[o] = s;
    }
}

// ---------------- compose conv3*conv4*avgpool -> 6x6 stride-2 conv ----------------
__global__ void k_compose34(const float* __restrict__ c3w, const float* __restrict__ c3b,
                            const float* __restrict__ c4w, const float* __restrict__ c4b) {
    int idx = blockIdx.x * blockDim.x + threadIdx.x;
    if (idx < 11664) {
        int oc = idx % 18;
        int t = idx / 18;        // ci*36 + u*6 + v
        int ci = t / 36;
        int u = (t % 36) / 6;
        int v = t % 6;
        float s = 0.f;
        for (int m = 0; m < 18; m++) {
            for (int a = 0; a < 2; a++) {
                int y = u - a;
                if (y < 0 || y > 4) continue;
                for (int b = 0; b < 2; b++) {
                    int x = v - b;
                    if (x < 0 || x > 4) continue;
                    int ky_lo = y > 2 ? y - 2 : 0, ky_hi = y < 2 ? y : 2;
                    int kx_lo = x > 2 ? x - 2 : 0, kx_hi = x < 2 ? x : 2;
                    for (int ky = ky_lo; ky <= ky_hi; ky++)
                        for (int kx = kx_lo; kx <= kx_hi; kx++)
                            s += c4w[((oc * 18 + m) * 3 + ky) * 3 + kx] *
                                 c3w[((m * 18 + ci) * 3 + (y - ky)) * 3 + (x - kx)];
                }
            }
        }
        g_w34c[idx] = 0.25f * s;
    } else if (idx < 11682) {
        int oc = idx - 11664;
        float s = c4b[oc];
        for (int m = 0; m < 18; m++) {
            float t4 = 0.f;
            for (int q = 0; q < 9; q++) t4 += c4w[(oc * 18 + m) * 9 + q];
            s += c3b[m] * t4;
        }
        g_b34[oc] = s;
    }
}

// ---------------- convA (R12 verbatim): composed 5x5 (6->18) + maxpool2 ----------------
// grid (5 rowbands, 1024 pairs), 512 thr, 2 CTAs/SM
// smem: wAts 21600 | b2s 96 | inP 6*16*64 ull = 49152  => 70848
#define SMEM_A 70848

__global__ __launch_bounds__(512, 2) void k_convA(const float* __restrict__ states) {
    extern __shared__ char smA[];
    ull* wAts = (ull*)smA;              // [ci*25+k][oc]
    float* b2s = (float*)(smA + 21600);
    ull* inP = (ull*)(smA + 21696);
    const int tid = threadIdx.x;
    const int band = blockIdx.x;        // 0..4, 6 pooled rows each
    const int pair = blockIdx.y;
    const int ir0 = 12 * band;

    for (int i = tid; i < 2700; i += 512) wAts[i] = g_wAt[i];
    if (tid < 18) b2s[tid] = g_b2[tid];
    {
        const float4* s0 = (const float4*)(states) + (size_t)pair * 12288;
        for (int i = tid; i < 1536; i += 512) {
            int c4 = i & 15, r = (i >> 4) & 15, ci = i >> 8;
            int goff = (ci * 64 + ir0 + r) * 16 + c4;
            float4 a = s0[goff], b = s0[goff + 6144];
            ull* d = inP + (ci << 10) + (r << 6) + (c4 << 2);
            d[0] = pk2(a.x, b.x); d[1] = pk2(a.y, b.y);
            d[2] = pk2(a.z, b.z); d[3] = pk2(a.w, b.w);
        }
    }
    __syncthreads();

    // strips: pl(6) x blk(15) x oc(18) = 1620; oc fastest
    for (int t = tid; t < 1620; t += 512) {
        int oc = t % 18;
        int r2 = t / 18;
        int blk = r2 % 15;
        int pl = r2 / 15;
        int c0 = blk * 4;

        ull acc[2][4];
#pragma unroll
        for (int r = 0; r < 2; r++)
#pragma unroll
            for (int j = 0; j < 4; j++) acc[r][j] = 0ull;

#pragma unroll 1
        for (int ci = 0; ci < 6; ci++) {
            const ull* rb = inP + (ci << 10) + (pl << 7) + c0;
            const ull* wb = wAts + ci * 450 + oc;
            ull wn0 = 0, wn1 = 0, wn2 = 0, wn3 = 0, wn4 = 0;
            ull wp0 = 0, wp1 = 0, wp2 = 0, wp3 = 0, wp4 = 0;
#pragma unroll
            for (int iy = 0; iy < 6; iy++) {
                ull v[8];
                {
                    const ulonglong2* vp = (const ulonglong2*)(rb + (iy << 6));
#pragma unroll
                    for (int j = 0; j < 4; j++) { ulonglong2 q = vp[j]; v[2 * j] = q.x; v[2 * j + 1] = q.y; }
                }
                if (iy < 5) {
                    wn0 = wb[(iy * 5) * 18];
                    wn1 = wb[(iy * 5 + 1) * 18];
                    wn2 = wb[(iy * 5 + 2) * 18];
                    wn3 = wb[(iy * 5 + 3) * 18];
                    wn4 = wb[(iy * 5 + 4) * 18];
#pragma unroll
                    for (int j = 0; j < 4; j++) {
                        ffma2(acc[0][j], wn0, v[j]);
                        ffma2(acc[0][j], wn1, v[j + 1]);
                        ffma2(acc[0][j], wn2, v[j + 2]);
                        ffma2(acc[0][j], wn3, v[j + 3]);
                        ffma2(acc[0][j], wn4, v[j + 4]);
                    }
                }
                if (iy >= 1) {
#pragma unroll
                    for (int j = 0; j < 4; j++) {
                        ffma2(acc[1][j], wp0, v[j]);
                        ffma2(acc[1][j], wp1, v[j + 1]);
                        ffma2(acc[1][j], wp2, v[j + 2]);
                        ffma2(acc[1][j], wp3, v[j + 3]);
                        ffma2(acc[1][j], wp4, v[j + 4]);
                    }
                }
                wp0 = wn0; wp1 = wn1; wp2 = wn2; wp3 = wn3; wp4 = wn4;
            }
        }
        float bias = b2s[oc];
        int prow = band * 6 + pl;
        ull* op = g_pool1p + (((size_t)pair * 18 + oc) * 30 + prow) * 30 + blk * 2;
#pragma unroll
        for (int p = 0; p < 2; p++) {
            float2 a0 = upk2(acc[0][2 * p]), a1 = upk2(acc[0][2 * p + 1]);
            float2 b0 = upk2(acc[1][2 * p]), b1 = upk2(acc[1][2 * p + 1]);
            float mx = fmaxf(fmaxf(a0.x, a1.x), fmaxf(b0.x, b1.x)) + bias;
            float my = fmaxf(fmaxf(a0.y, a1.y), fmaxf(b0.y, b1.y)) + bias;
            op[p] = pk2(mx, my);
        }
    }
}

// ---------------- conv34c: composed 6x6 stride-2 conv (18->18), 30x30 pool1 -> 13x13 feat ----------------
// grid (2 rowhalves, 1024 pairs), 512 thr, 2 CTAs/SM
// smem: wS 5832 floats (23328B, one 9-ci phase) | b34 96 | dS 18*18*30 ull (77760B) => 101184
#define SMEM_C34 101184

__global__ __launch_bounds__(512, 2) void k_conv34c() {
    extern __shared__ char smE[];
    float* wS = (float*)smE;               // [(ci_l*36 + k)*18 + oc]
    float* bS = (float*)(smE + 23328);
    ull* dS = (ull*)(smE + 23424);         // [ci][row][col], stride 30
    const int tid = threadIdx.x;
    const int hf = blockIdx.x;             // 0: pr 0..6 (rows 0..17), 1: pr 7..12 (rows 14..29)
    const int pair = blockIdx.y;
    const int ir0 = hf ? 14 : 0;
    const int nr = hf ? 16 : 18;

    if (tid < 18) bS[tid] = g_b34[tid];
    {
        const ull* src = g_pool1p + (size_t)pair * 16200;
        int per_ci = nr * 30;
        int total = 18 * per_ci;
        for (int e = tid; e < total; e += 512) {
            int ci = e / per_ci;
            int rem = e - ci * per_ci;
            int r = rem / 30, c = rem - r * 30;
            dS[ci * 540 + r * 30 + c] = src[(ci * 30 + ir0 + r) * 30 + c];
        }
    }
    for (int i = tid; i < 5832; i += 512) wS[i] = g_w34c[i];
    __syncthreads();

    const int nstrip = (hf ? 6 : 7) * 4 * 18;
    int oc = 0, cq = 0, pr_l = 0;
    if (tid < nstrip) {
        oc = tid % 18;
        int r2 = tid / 18;
        cq = r2 % 4;
        pr_l = r2 / 4;
    }
    const int c0 = 6 * cq;

    ull acc[4];
#pragma unroll
    for (int j = 0; j < 4; j++) acc[j] = 0ull;

#pragma unroll 1
    for (int cp = 0; cp < 2; cp++) {
        if (cp == 1) {
            __syncthreads();
            for (int i = tid; i < 5832; i += 512) wS[i] = g_w34c[5832 + i];
            __syncthreads();
        }
        if (tid < nstrip) {
#pragma unroll 1
            for (int cil = 0; cil < 9; cil++) {
                int ci = cp * 9 + cil;
                const ull* rb = dS + ci * 540 + (2 * pr_l) * 30 + c0;
                const float* wb = wS + cil * 648 + oc;
#pragma unroll
                for (int u = 0; u < 6; u++) {
                    ull v[12];
                    {
                        const ull* vp = rb + u * 30;
#pragma unroll
                        for (int j = 0; j < 12; j++) v[j] = vp[j];
                    }
#pragma unroll
                    for (int kx = 0; kx < 6; kx++) {
                        float wf = wb[(u * 6 + kx) * 18];
                        ull w = pk2(wf, wf);
                        ffma2(acc[0], w, v[kx]);
                        ffma2(acc[1], w, v[kx + 2]);
                        ffma2(acc[2], w, v[kx + 4]);
                        ffma2(acc[3], w, v[kx + 6]);
                    }
                }
            }
        }
    }

    if (tid < nstrip) {
        float b = bS[oc];
        int pr = 7 * hf + pr_l;
        float* f0 = g_feat + (size_t)(2 * pair) * 3042 + (oc * 13 + pr) * 13 + 3 * cq;
        float* f1 = f0 + 3042;
        int plo = cq ? 1 : 0;
#pragma unroll
        for (int pp = 0; pp < 4; pp++) {
            if (pp >= plo) {
                float2 vv = upk2(acc[pp]);
                f0[pp] = vv.x + b;
                f1[pp] = vv.y + b;
            }
        }
    }
}

// ---------------- MLP + expert routing + softmax, 8 samples/CTA (R4 verbatim) ----------------
#define SMEM_M ((8 * 3076 + 64 * 132 + 8 * 66 + 512 + 64) * 4)

__global__ __launch_bounds__(512, 1) void k_mlp(const float* __restrict__ scores, const float* __restrict__ times,
                                                const int* __restrict__ agents,
                                                const float* __restrict__ l1w, const float* __restrict__ l1b,
                                                const float* __restrict__ l2w, const float* __restrict__ l2b,
                                                const float* __restrict__ agw, const float* __restrict__ agb,
                                                float* __restrict__ out) {
    extern __shared__ float smM[];
    float* featS = smM;
    float* wT = featS + 8 * 3076;
    float* h1S = wT + 64 * 132;
    float* h2S = h1S + 8 * 66;
    float* logS = h2S + 512;
    const int tid = threadIdx.x;
    const int sb = blockIdx.x * 8;

    for (int i = tid; i < 8 * 1521; i += 512) {
        int s = i / 1521;
        int r = i - s * 1521;
        ((float2*)(featS + s * 3076))[r] = ((const float2*)(g_feat + (size_t)(sb + s) * 3042))[r];
    }
    if (tid < 8) {
        featS[tid * 3076 + 3042] = scores[sb + tid];
        featS[tid * 3076 + 3043] = times[sb + tid];
    }
    if (tid >= 32 && tid < 288) {
        int j = tid - 32;
        featS[(j >> 5) * 3076 + 3044 + (j & 31)] = 0.f;
    }
    __syncthreads();

    const int s = tid & 7, o = tid >> 3;
    ull f0a = 0, f1a = 0, f2a = 0, f3a = 0;
#pragma unroll 1
    for (int kt = 0; kt < 24; kt++) {
        int k0 = kt << 7;
        for (int i = tid; i < 8192; i += 512) {
            int oo = i >> 7, kk = i & 127;
            int k = k0 + kk;
            wT[oo * 132 + kk] = (k < 3044) ? l1w[oo * 3044 + k] : 0.f;
        }
        __syncthreads();
        const ull* fr = (const ull*)(featS + s * 3076 + k0);
        const ull* wr = (const ull*)(wT + o * 132);
#pragma unroll
        for (int kk = 0; kk < 64; kk += 4) {
            ffma2(f0a, fr[kk], wr[kk]);
            ffma2(f1a, fr[kk + 1], wr[kk + 1]);
            ffma2(f2a, fr[kk + 2], wr[kk + 2]);
            ffma2(f3a, fr[kk + 3], wr[kk + 3]);
        }
        __syncthreads();
    }
    {
        float2 a = upk2(f0a), b = upk2(f1a), c = upk2(f2a), d = upk2(f3a);
        float acc = (a.x + a.y) + (b.x + b.y) + (c.x + c.y) + (d.x + d.y);
        h1S[s * 66 + o] = tanhf(acc + l1b[o]);
    }
    __syncthreads();
    {
        const ull* hr = (const ull*)(h1S + s * 66);
        const ull* w2 = (const ull*)(l2w + o * 64);
        ull a0 = 0, a1 = 0;
#pragma unroll
        for (int kk = 0; kk < 32; kk += 2) {
            ffma2(a0, hr[kk], w2[kk]);
            ffma2(a1, hr[kk + 1], w2[kk + 1]);
        }
        float2 a = upk2(a0), b = upk2(a1);
        h2S[s * 64 + o] = tanhf(a.x + a.y + b.x + b.y + l2b[o]);
    }
    __syncthreads();
    if (tid < 40) {
        int ss = tid / 5, oo = tid - ss * 5;
        int ag = agents[sb + ss];
        const float* W = agw + (ag * 5 + oo) * 64;
        const float* h = h2S + ss * 64;
        float a = agb[ag * 5 + oo];
#pragma unroll
        for (int k = 0; k < 64; k++) a += W[k] * h[k];
        logS[ss * 8 + oo] = a;
    }
    __syncthreads();
    if (tid < 8) {
        float m = -1e30f;
        for (int i = 0; i < 5; i++) m = fmaxf(m, logS[tid * 8 + i]);
        float e[5], sum = 0.f;
        for (int i = 0; i < 5; i++) { e[i] = expf(logS[tid * 8 + i] - m); sum += e[i]; }
        float inv = 1.f / sum;
        for (int i = 0; i < 5; i++) out[(sb + tid) * 5 + i] = e[i] * inv;
    }
}

// ---------------- launch ----------------
extern "C" void kernel_launch(void* const* d_in, const int* in_sizes, int n_in,
                              void* d_out, int out_size) {
    const float* states = (const float*)d_in[0];
    const float* scores = (const float*)d_in[1];
    const float* times  = (const float*)d_in[2];
    const int*   agents = (const int*)d_in[3];
    const float* c1w = (const float*)d_in[4];
    const float* c1b = (const float*)d_in[5];
    const float* c2w = (const float*)d_in[6];
    const float* c2b = (const float*)d_in[7];
    const float* c3w = (const float*)d_in[8];
    const float* c3b = (const float*)d_in[9];
    const float* c4w = (const float*)d_in[10];
    const float* c4b = (const float*)d_in[11];
    const float* l1w = (const float*)d_in[12];
    const float* l1b = (const float*)d_in[13];
    const float* l2w = (const float*)d_in[14];
    const float* l2b = (const float*)d_in[15];
    const float* agw = (const float*)d_in[16];
    const float* agb = (const float*)d_in[17];
    float* out = (float*)d_out;

    cudaFuncSetAttribute(k_convA, cudaFuncAttributeMaxDynamicSharedMemorySize, SMEM_A);
    cudaFuncSetAttribute(k_conv34c, cudaFuncAttributeMaxDynamicSharedMemorySize, SMEM_C34);
    cudaFuncSetAttribute(k_mlp, cudaFuncAttributeMaxDynamicSharedMemorySize, SMEM_M);

    k_compose<<<3, 1024>>>(c1w, c1b, c2w, c2b);
    k_compose34<<<23, 512>>>(c3w, c3b, c4w, c4b);
    k_convA<<<dim3(5, 1024), 512, SMEM_A>>>(states);
    k_conv34c<<<dim3(2, 1024), 512, SMEM_C34>>>();
    k_mlp<<<256, 512, SMEM_M>>>(scores, times, agents, l1w, l1b, l2w, l2b, agw, agb, out);
}